// round 14
// baseline (speedup 1.0000x reference)
#include <cuda_runtime.h>
#include <cuda_bf16.h>
#include <cstddef>
#include <cstdint>

#define N_NODESC 100000
#define N_EDGESC 3200000
#define N_GRAPHSC 2048
#define DIM 256
#define EPSC 1e-5f

// ---------------- scratch ----------------
__device__ float g_z[(size_t)N_NODESC * DIM];
__device__ float g_y[(size_t)N_NODESC * 2 * DIM];
__device__ __nv_bfloat16 g_hb[(size_t)N_NODESC * DIM];   // bf16 node features
__device__ __nv_bfloat16 g_bondb[2000 * DIM];            // bf16 combined bond tables
__device__ float g_w[393216];            // tf32-rounded weights (linear): w1|w2|w3|w4
__device__ int   g_deg[N_NODESC + 1];
__device__ int   g_off[N_NODESC + 1];
__device__ int   g_pos[N_NODESC];
__device__ __align__(16) int2 g_csr[N_EDGESC];           // (src*512, key*512) byte offsets
__device__ float g_sum[1024];
__device__ float g_sq[1024];
__device__ float g_scale[512];
__device__ float g_shift[512];

__device__ __forceinline__ void red_v2(float* addr, float a, float b) {
    asm volatile("red.global.add.v2.f32 [%0], {%1,%2};"
                 :: "l"(addr), "f"(a), "f"(b) : "memory");
}
__device__ __forceinline__ float to_tf32(float x) {
    uint32_t r;
    asm("cvt.rna.tf32.f32 %0, %1;" : "=r"(r) : "f"(x));
    return __uint_as_float(r);
}
__device__ __forceinline__ void mma_tf32(float c[4], const uint32_t a[4], const uint32_t b[2]) {
    asm volatile(
        "mma.sync.aligned.m16n8k8.row.col.f32.tf32.tf32.f32 "
        "{%0,%1,%2,%3}, {%4,%5,%6,%7}, {%8,%9}, {%0,%1,%2,%3};"
        : "+f"(c[0]), "+f"(c[1]), "+f"(c[2]), "+f"(c[3])
        : "r"(a[0]), "r"(a[1]), "r"(a[2]), "r"(a[3]), "r"(b[0]), "r"(b[1]));
}
__device__ __forceinline__ void cp_async16(void* smemp, const void* gmem) {
    unsigned s = (unsigned)__cvta_generic_to_shared(smemp);
    asm volatile("cp.async.cg.shared.global [%0], [%1], 16;" :: "r"(s), "l"(gmem));
}
__device__ __forceinline__ void cp_commit() { asm volatile("cp.async.commit_group;"); }
__device__ __forceinline__ void cp_wait0()  { asm volatile("cp.async.wait_group 0;"); }

// accumulate relu(h+bond) for 8 bf16 features packed in uint4
__device__ __forceinline__ void acc_edge(float acc[8], uint4 h, uint4 b) {
    const __nv_bfloat162 z2 = __float2bfloat162_rn(0.f);
    __nv_bfloat162 m;
    float2 v;
    m = __hmax2(__hadd2(*(const __nv_bfloat162*)&h.x, *(const __nv_bfloat162*)&b.x), z2);
    v = __bfloat1622float2(m); acc[0] += v.x; acc[1] += v.y;
    m = __hmax2(__hadd2(*(const __nv_bfloat162*)&h.y, *(const __nv_bfloat162*)&b.y), z2);
    v = __bfloat1622float2(m); acc[2] += v.x; acc[3] += v.y;
    m = __hmax2(__hadd2(*(const __nv_bfloat162*)&h.z, *(const __nv_bfloat162*)&b.z), z2);
    v = __bfloat1622float2(m); acc[4] += v.x; acc[5] += v.y;
    m = __hmax2(__hadd2(*(const __nv_bfloat162*)&h.w, *(const __nv_bfloat162*)&b.w), z2);
    v = __bfloat1622float2(m); acc[6] += v.x; acc[7] += v.y;
}

// ---------------- mega setup ----------------
__global__ void mega_setup(
    const int* __restrict__ x, const float* __restrict__ atom,
    const float* __restrict__ be1, const float* __restrict__ be2,
    const float* __restrict__ w1, const float* __restrict__ w2,
    const float* __restrict__ w3, const float* __restrict__ w4,
    const int* __restrict__ ei, float* __restrict__ out) {
    int b = blockIdx.x;
    int t = threadIdx.x;
    if (b < 25000) {
        __shared__ int xi[4][9];
        if (t < 36) xi[t / 9][t % 9] = x[(b * 4 + t / 9) * 9 + (t % 9)];
        __syncthreads();
        int sub = t >> 6;
        int fg = (t & 63) * 4;
        size_t node = (size_t)b * 4 + sub;
        float4 s = make_float4(0.f, 0.f, 0.f, 0.f);
#pragma unroll
        for (int c = 0; c < 9; c++) {
            float4 v = *(const float4*)(atom + ((size_t)(c * 100 + xi[sub][c])) * DIM + fg);
            s.x += v.x; s.y += v.y; s.z += v.z; s.w += v.w;
        }
        uint2 packed;
        *(__nv_bfloat162*)&packed.x = __floats2bfloat162_rn(s.x, s.y);
        *(__nv_bfloat162*)&packed.y = __floats2bfloat162_rn(s.z, s.w);
        *(uint2*)(g_hb + node * DIM + fg) = packed;
    } else if (b < 27000) {
        int bb = b - 25000;
        const float* be = (bb < 1000) ? be1 : be2;
        int k = (bb < 1000) ? bb : bb - 1000;
        int a0 = k / 100, a1 = (k / 10) % 10, a2 = k % 10;
        float v = be[(size_t)(0 * 10 + a0) * DIM + t]
                + be[(size_t)(1 * 10 + a1) * DIM + t]
                + be[(size_t)(2 * 10 + a2) * DIM + t];
        g_bondb[(size_t)bb * DIM + t] = __float2bfloat16(v);
    } else if (b < 27512) {
        int i = (b - 27000) * 256 + t;
        ((float4*)out)[i] = make_float4(0.f, 0.f, 0.f, 0.f);
    } else if (b < 29048) {
        int i = (b - 27512) * 256 + t;
        const float* src;
        int off;
        if (i < 131072)      { src = w1; off = 0; }
        else if (i < 262144) { src = w2; off = 131072; }
        else if (i < 327680) { src = w3; off = 262144; }
        else                 { src = w4; off = 327680; }
        g_w[i] = to_tf32(src[i - off]);
    } else {
        int e = (b - 29048) * 256 + t;
        if (e < N_EDGESC) atomicAdd(&g_deg[__ldg(ei + N_EDGESC + e)], 1);
    }
}

// ---------------- scan offsets (+ zero stats) ----------------
__global__ void scan_offsets() {
    const int CH = 98;
    __shared__ int ssum[1024];
    int t = threadIdx.x;
    g_sum[t] = 0.f;
    g_sq[t] = 0.f;
    int base = t * CH;
    int local = 0;
    for (int i = 0; i < CH; i++) {
        int idx = base + i;
        if (idx <= N_NODESC) local += g_deg[idx];
    }
    ssum[t] = local;
    __syncthreads();
    for (int off = 1; off < 1024; off <<= 1) {
        int v = (t >= off) ? ssum[t - off] : 0;
        __syncthreads();
        if (t >= off) ssum[t] += v;
        __syncthreads();
    }
    int run = (t == 0) ? 0 : ssum[t - 1];
    for (int i = 0; i < CH; i++) {
        int idx = base + i;
        if (idx <= N_NODESC) {
            int d = g_deg[idx];
            g_off[idx] = run;
            if (idx < N_NODESC) g_pos[idx] = run;
            run += d;
        }
    }
}

// ---------------- fill CSR: byte offsets (+ re-zero deg) ----------------
__global__ void fill_csr(const int* __restrict__ ei, const int* __restrict__ ea) {
    int e = blockIdx.x * blockDim.x + threadIdx.x;
    if (e <= N_NODESC) g_deg[e] = 0;
    if (e >= N_EDGESC) return;
    int src = __ldg(ei + e);
    int dst = __ldg(ei + N_EDGESC + e);
    int key = __ldg(ea + (size_t)e * 3 + 0) * 100
            + __ldg(ea + (size_t)e * 3 + 1) * 10
            + __ldg(ea + (size_t)e * 3 + 2);
    int slot = atomicAdd(&g_pos[dst], 1);
    g_csr[slot] = make_int2(src << 9, key << 9);
}

// ---------------- gather (bf16x2 SIMD, byte-offset CSR, unroll 4) ----------------
__global__ __launch_bounds__(256, 6) void gather_mp(const __nv_bfloat16* __restrict__ bond) {
    int n = (int)(((size_t)blockIdx.x * blockDim.x + threadIdx.x) >> 5);
    if (n >= N_NODESC) return;
    int lane = threadIdx.x & 31;
    unsigned fo2 = lane * 16;
    const char* hbase = (const char*)g_hb + fo2;
    const char* bbase = (const char*)bond + fo2;
    float acc[8];
    {
        uint4 hs = *(const uint4*)(hbase + ((unsigned)n << 9));
        float2 v;
        v = __bfloat1622float2(*(const __nv_bfloat162*)&hs.x); acc[0] = v.x; acc[1] = v.y;
        v = __bfloat1622float2(*(const __nv_bfloat162*)&hs.y); acc[2] = v.x; acc[3] = v.y;
        v = __bfloat1622float2(*(const __nv_bfloat162*)&hs.z); acc[4] = v.x; acc[5] = v.y;
        v = __bfloat1622float2(*(const __nv_bfloat162*)&hs.w); acc[6] = v.x; acc[7] = v.y;
    }
    int p = g_off[n], pe = g_off[n + 1];
    if (p < pe && (p & 1)) {
        int2 sk = __ldg(&g_csr[p]);
        uint4 h = *(const uint4*)(hbase + (unsigned)sk.x);
        uint4 b = *(const uint4*)(bbase + (unsigned)sk.y);
        acc_edge(acc, h, b);
        p++;
    }
    for (; p + 4 <= pe; p += 4) {
        int4 e01 = *(const int4*)&g_csr[p];
        int4 e23 = *(const int4*)&g_csr[p + 2];
        uint4 h0 = *(const uint4*)(hbase + (unsigned)e01.x);
        uint4 b0 = *(const uint4*)(bbase + (unsigned)e01.y);
        uint4 h1 = *(const uint4*)(hbase + (unsigned)e01.z);
        uint4 b1 = *(const uint4*)(bbase + (unsigned)e01.w);
        uint4 h2 = *(const uint4*)(hbase + (unsigned)e23.x);
        uint4 b2 = *(const uint4*)(bbase + (unsigned)e23.y);
        uint4 h3 = *(const uint4*)(hbase + (unsigned)e23.z);
        uint4 b3 = *(const uint4*)(bbase + (unsigned)e23.w);
        acc_edge(acc, h0, b0);
        acc_edge(acc, h1, b1);
        acc_edge(acc, h2, b2);
        acc_edge(acc, h3, b3);
    }
    for (; p < pe; p++) {
        int2 sk = __ldg(&g_csr[p]);
        uint4 h = *(const uint4*)(hbase + (unsigned)sk.x);
        uint4 b = *(const uint4*)(bbase + (unsigned)sk.y);
        acc_edge(acc, h, b);
    }
    float* zd = g_z + (size_t)n * DIM + lane * 8;
    *(float4*)(zd)     = make_float4(acc[0], acc[1], acc[2], acc[3]);
    *(float4*)(zd + 4) = make_float4(acc[4], acc[5], acc[6], acc[7]);
}

// ---------------- BN finalize ----------------
__global__ void finstats(const float* __restrict__ gamma, const float* __restrict__ beta,
                         int Dh, int off) {
    int c = blockIdx.x * 256 + threadIdx.x;
    if (c >= Dh) return;
    float inv_n = 1.0f / (float)N_NODESC;
    float mu = g_sum[off + c] * inv_n;
    float var = g_sq[off + c] * inv_n - mu * mu;
    float rs = rsqrtf(var + EPSC);
    float sc = rs * gamma[c];
    g_scale[c] = sc;
    g_shift[c] = beta[c] - mu * sc;
}

// ---------------- tf32 tensor-core GEMM 128x128x32, dynamic smem, conflict-free ----------------
// A rows padded to 36 floats (banks 4lq+lr bijective); B rows 136 (banks 8lr+lq bijective).
template <bool TRANSFORM, bool RELU, int STATS, bool STOREC, bool BF16OUT, bool POOL>
__global__ __launch_bounds__(256, 2) void gemm_tc(
    const float* __restrict__ A, const float* __restrict__ B,
    const float* __restrict__ bias, float* __restrict__ C,
    const int* __restrict__ batch, float* __restrict__ pool_out,
    int M, int K, int Nc) {
    const int BK = 32;
    extern __shared__ float sm[];
    // As buf: [128][36] floats (4608); Bs buf: [32][136] floats (4352)
    float* Asb[2] = { sm, sm + 4608 };
    float* Bsb[2] = { sm + 9216, sm + 9216 + 4352 };
    int* sbatch = (int*)(sm + 9216 + 8704);

    int tid = threadIdx.x;
    int lane = tid & 31;
    int wid = tid >> 5;
    int wm = wid & 1;
    int wn = wid >> 1;
    int bm = blockIdx.y * 128;
    int bn = blockIdx.x * 128;

    if (POOL && tid < 128) sbatch[tid] = (bm + tid < M) ? batch[bm + tid] : -1;

    // A loader: row ar, k-half akb (16 k each, 4 float4)
    int ar = tid >> 1;
    int akb = (tid & 1) * 16;
    bool aok = (bm + ar) < M;
    const float* arow = A + (size_t)(bm + ar) * K + akb;
    // B loader: row br (0..31), col chunk bq (16 floats)
    int br = tid >> 3;
    int bq = (tid & 7) * 16;

    float c[4][4][4];
#pragma unroll
    for (int mt = 0; mt < 4; mt++)
#pragma unroll
        for (int nt = 0; nt < 4; nt++)
#pragma unroll
            for (int r = 0; r < 4; r++) c[mt][nt][r] = 0.f;

    float4 a4s[4];

    auto ldg_a = [&](int ck) {
#pragma unroll
        for (int j = 0; j < 4; j++) {
            a4s[j] = aok ? *(const float4*)(arow + ck * BK + 4 * j)
                         : make_float4(0.f, 0.f, 0.f, 0.f);
            if (TRANSFORM) {
                int kb = ck * BK + akb + 4 * j;
                a4s[j].x = fmaxf(a4s[j].x * g_scale[kb + 0] + g_shift[kb + 0], 0.f);
                a4s[j].y = fmaxf(a4s[j].y * g_scale[kb + 1] + g_shift[kb + 1], 0.f);
                a4s[j].z = fmaxf(a4s[j].z * g_scale[kb + 2] + g_shift[kb + 2], 0.f);
                a4s[j].w = fmaxf(a4s[j].w * g_scale[kb + 3] + g_shift[kb + 3], 0.f);
            }
        }
    };
    auto sts_a = [&](int buf) {
        float* dst = Asb[buf] + ar * 36 + akb;
#pragma unroll
        for (int j = 0; j < 4; j++)
            *(float4*)(dst + 4 * j) = make_float4(to_tf32(a4s[j].x), to_tf32(a4s[j].y),
                                                  to_tf32(a4s[j].z), to_tf32(a4s[j].w));
    };
    auto ldb_async = [&](int buf, int ck) {
        const float* src = B + (size_t)(ck * BK + br) * Nc + bn + bq;
        float* dst = Bsb[buf] + br * 136 + bq;
#pragma unroll
        for (int j = 0; j < 4; j++)
            cp_async16(dst + 4 * j, src + 4 * j);
        cp_commit();
    };

    ldb_async(0, 0);
    ldg_a(0);
    sts_a(0);
    cp_wait0();
    __syncthreads();

    int nIter = K / BK;
    int lq = lane >> 2;
    int lr = lane & 3;
    for (int it = 0; it < nIter; it++) {
        int cur = it & 1, nxt = cur ^ 1;
        bool more = (it + 1 < nIter);
        if (more) {
            ldg_a(it + 1);
            ldb_async(nxt, it + 1);
        }
        const float* Ac = Asb[cur];
        const float* Bc = Bsb[cur];
#pragma unroll
        for (int ks = 0; ks < 4; ks++) {
            int k0 = ks * 8;
            uint32_t bf[4][2];
#pragma unroll
            for (int nt = 0; nt < 4; nt++) {
                int ncol = wn * 32 + nt * 8 + lq;
                bf[nt][0] = __float_as_uint(Bc[(k0 + lr) * 136 + ncol]);
                bf[nt][1] = __float_as_uint(Bc[(k0 + 4 + lr) * 136 + ncol]);
            }
#pragma unroll
            for (int mt = 0; mt < 4; mt++) {
                int mrow = wm * 64 + mt * 16 + lq;
                uint32_t af[4];
                af[0] = __float_as_uint(Ac[mrow * 36 + k0 + lr]);
                af[1] = __float_as_uint(Ac[(mrow + 8) * 36 + k0 + lr]);
                af[2] = __float_as_uint(Ac[mrow * 36 + k0 + 4 + lr]);
                af[3] = __float_as_uint(Ac[(mrow + 8) * 36 + k0 + 4 + lr]);
#pragma unroll
                for (int nt = 0; nt < 4; nt++) mma_tf32(c[mt][nt], af, bf[nt]);
            }
        }
        if (more) {
            sts_a(nxt);
            cp_wait0();
        }
        __syncthreads();
    }

    // ---------------- epilogue ----------------
    float2 bias2[4];
    int cbase[4];
#pragma unroll
    for (int nt = 0; nt < 4; nt++) {
        cbase[nt] = bn + wn * 32 + nt * 8 + lr * 2;
        bias2[nt] = *(const float2*)(bias + cbase[nt]);
    }

    float sx[4][2], qx[4][2];
    if (STATS >= 0) {
#pragma unroll
        for (int nt = 0; nt < 4; nt++) { sx[nt][0] = sx[nt][1] = 0.f; qx[nt][0] = qx[nt][1] = 0.f; }
    }

    float pl[4][2];
    int curb = -1;
    if (POOL) {
#pragma unroll
        for (int nt = 0; nt < 4; nt++) { pl[nt][0] = 0.f; pl[nt][1] = 0.f; }
    }

#pragma unroll
    for (int mt = 0; mt < 4; mt++) {
#pragma unroll
        for (int half = 0; half < 2; half++) {
            int rloc = wm * 64 + mt * 16 + lq + half * 8;
            int r = bm + rloc;
            if (r >= M) continue;
            float v[4][2];
#pragma unroll
            for (int nt = 0; nt < 4; nt++) {
                v[nt][0] = c[mt][nt][half * 2 + 0] + bias2[nt].x;
                v[nt][1] = c[mt][nt][half * 2 + 1] + bias2[nt].y;
                if (RELU) {
                    v[nt][0] = fmaxf(v[nt][0], 0.f);
                    v[nt][1] = fmaxf(v[nt][1], 0.f);
                }
                if (STATS >= 0) {
                    sx[nt][0] += v[nt][0]; sx[nt][1] += v[nt][1];
                    qx[nt][0] += v[nt][0] * v[nt][0]; qx[nt][1] += v[nt][1] * v[nt][1];
                }
            }
            if (STOREC) {
#pragma unroll
                for (int nt = 0; nt < 4; nt++)
                    *(float2*)(C + (size_t)r * Nc + cbase[nt]) = make_float2(v[nt][0], v[nt][1]);
            }
            if (BF16OUT) {
#pragma unroll
                for (int nt = 0; nt < 4; nt++)
                    *(__nv_bfloat162*)(g_hb + (size_t)r * DIM + cbase[nt]) =
                        __floats2bfloat162_rn(v[nt][0], v[nt][1]);
            }
            if (POOL) {
                int bg = sbatch[rloc];
                if (bg != curb) {
                    if (curb >= 0) {
#pragma unroll
                        for (int nt = 0; nt < 4; nt++) {
                            red_v2(pool_out + (size_t)curb * DIM + cbase[nt], pl[nt][0], pl[nt][1]);
                            pl[nt][0] = 0.f; pl[nt][1] = 0.f;
                        }
                    }
                    curb = bg;
                }
#pragma unroll
                for (int nt = 0; nt < 4; nt++) { pl[nt][0] += v[nt][0]; pl[nt][1] += v[nt][1]; }
            }
        }
    }
    if (POOL && curb >= 0) {
#pragma unroll
        for (int nt = 0; nt < 4; nt++)
            red_v2(pool_out + (size_t)curb * DIM + cbase[nt], pl[nt][0], pl[nt][1]);
    }

    if (STATS >= 0) {
#pragma unroll
        for (int nt = 0; nt < 4; nt++) {
#pragma unroll
            for (int h = 0; h < 2; h++) {
#pragma unroll
                for (int off = 4; off < 32; off <<= 1) {
                    sx[nt][h] += __shfl_xor_sync(0xffffffffu, sx[nt][h], off);
                    qx[nt][h] += __shfl_xor_sync(0xffffffffu, qx[nt][h], off);
                }
            }
        }
        if (lane < 4) {
#pragma unroll
            for (int nt = 0; nt < 4; nt++) {
                atomicAdd(&g_sum[STATS + cbase[nt] + 0], sx[nt][0]);
                atomicAdd(&g_sum[STATS + cbase[nt] + 1], sx[nt][1]);
                atomicAdd(&g_sq[STATS + cbase[nt] + 0], qx[nt][0]);
                atomicAdd(&g_sq[STATS + cbase[nt] + 1], qx[nt][1]);
            }
        }
    }
}

// ---------------- launch ----------------
extern "C" void kernel_launch(void* const* d_in, const int* in_sizes, int n_in,
                              void* d_out, int out_size) {
    const int* x      = (const int*)d_in[0];
    const int* ei     = (const int*)d_in[1];
    const int* ea     = (const int*)d_in[2];
    const int* batch  = (const int*)d_in[3];
    const float* atom = (const float*)d_in[4];
    const float* be1  = (const float*)d_in[5];
    const float* be2  = (const float*)d_in[6];
    const float* c1_w1 = (const float*)d_in[7];
    const float* c1_b1 = (const float*)d_in[8];
    const float* c1_g  = (const float*)d_in[9];
    const float* c1_be = (const float*)d_in[10];
    const float* c1_w2 = (const float*)d_in[11];
    const float* c1_b2 = (const float*)d_in[12];
    const float* c2_w1 = (const float*)d_in[13];
    const float* c2_b1 = (const float*)d_in[14];
    const float* c2_g  = (const float*)d_in[15];
    const float* c2_be = (const float*)d_in[16];
    const float* c2_w2 = (const float*)d_in[17];
    const float* c2_b2 = (const float*)d_in[18];
    float* out = (float*)d_out;

    float *zz, *yz, *wz;
    __nv_bfloat16 *bbz;
    cudaGetSymbolAddress((void**)&zz, g_z);
    cudaGetSymbolAddress((void**)&yz, g_y);
    cudaGetSymbolAddress((void**)&wz, g_w);
    cudaGetSymbolAddress((void**)&bbz, g_bondb);

    const int M = N_NODESC;
    const int eb = (N_EDGESC + 255) / 256;
    const int gb = (N_NODESC * 32 + 255) / 256;
    const int mtiles = (M + 127) / 128;
    dim3 gA(4, mtiles);   // Nc=512
    dim3 gB(2, mtiles);   // Nc=256
    const int SMEMB = 72192;

    auto k1 = gemm_tc<false, false, 0,   true,  false, false>;
    auto k2 = gemm_tc<true,  true,  -1,  false, true,  false>;
    auto k3 = gemm_tc<false, false, 512, true,  false, false>;
    auto k4 = gemm_tc<true,  true,  -1,  false, false, true >;
    cudaFuncSetAttribute(k1, cudaFuncAttributeMaxDynamicSharedMemorySize, SMEMB);
    cudaFuncSetAttribute(k2, cudaFuncAttributeMaxDynamicSharedMemorySize, SMEMB);
    cudaFuncSetAttribute(k3, cudaFuncAttributeMaxDynamicSharedMemorySize, SMEMB);
    cudaFuncSetAttribute(k4, cudaFuncAttributeMaxDynamicSharedMemorySize, SMEMB);

    // idx: mega(0) scan(1) fill(2) gather1(3) <- ncu samples idx 3
    mega_setup<<<41548, 256>>>(x, atom, be1, be2, c1_w1, c1_w2, c2_w1, c2_w2, ei, out);
    scan_offsets<<<1, 1024>>>();
    fill_csr<<<eb, 256>>>(ei, ea);

    // ---- conv1 ----
    gather_mp<<<gb, 256>>>(bbz);
    k1<<<gA, 256, SMEMB>>>(zz, wz + 0, c1_b1, yz, nullptr, nullptr, M, 256, 512);
    finstats<<<2, 256>>>(c1_g, c1_be, 512, 0);
    k2<<<gB, 256, SMEMB>>>(yz, wz + 131072, c1_b2, nullptr, nullptr, nullptr, M, 512, 256);

    // ---- conv2 ----
    gather_mp<<<gb, 256>>>(bbz + (size_t)1000 * DIM);
    k3<<<gB, 256, SMEMB>>>(zz, wz + 262144, c2_b1, yz, nullptr, nullptr, M, 256, 256);
    finstats<<<1, 256>>>(c2_g, c2_be, 256, 512);
    k4<<<gB, 256, SMEMB>>>(yz, wz + 327680, c2_b2, nullptr, batch, out, M, 256, 256);
}

// round 15
// speedup vs baseline: 1.0881x; 1.0881x over previous
#include <cuda_runtime.h>
#include <cuda_bf16.h>
#include <cstddef>
#include <cstdint>

#define N_NODESC 100000
#define N_EDGESC 3200000
#define N_GRAPHSC 2048
#define DIM 256
#define EPSC 1e-5f

// ---------------- scratch ----------------
__device__ float g_z[(size_t)N_NODESC * DIM];
__device__ float g_y[(size_t)N_NODESC * 2 * DIM];
__device__ __nv_bfloat16 g_hb[(size_t)N_NODESC * DIM];   // bf16 node features
__device__ __nv_bfloat16 g_bondb[2000 * DIM];            // bf16 combined bond tables
__device__ float g_w[393216];            // tf32-rounded weights (linear): w1|w2|w3|w4
__device__ int   g_deg[N_NODESC + 1];
__device__ int   g_off[N_NODESC + 1];
__device__ int   g_pos[N_NODESC];
__device__ __align__(16) int2 g_csr[N_EDGESC];           // (src*512, key*512) byte offsets
__device__ float g_sum[1024];
__device__ float g_sq[1024];
__device__ float g_scale[512];
__device__ float g_shift[512];

__device__ __forceinline__ void red_v2(float* addr, float a, float b) {
    asm volatile("red.global.add.v2.f32 [%0], {%1,%2};"
                 :: "l"(addr), "f"(a), "f"(b) : "memory");
}
__device__ __forceinline__ float to_tf32(float x) {
    uint32_t r;
    asm("cvt.rna.tf32.f32 %0, %1;" : "=r"(r) : "f"(x));
    return __uint_as_float(r);
}
__device__ __forceinline__ void mma_tf32(float c[4], const uint32_t a[4], const uint32_t b[2]) {
    asm volatile(
        "mma.sync.aligned.m16n8k8.row.col.f32.tf32.tf32.f32 "
        "{%0,%1,%2,%3}, {%4,%5,%6,%7}, {%8,%9}, {%0,%1,%2,%3};"
        : "+f"(c[0]), "+f"(c[1]), "+f"(c[2]), "+f"(c[3])
        : "r"(a[0]), "r"(a[1]), "r"(a[2]), "r"(a[3]), "r"(b[0]), "r"(b[1]));
}
__device__ __forceinline__ void cp_async16(void* smemp, const void* gmem) {
    unsigned s = (unsigned)__cvta_generic_to_shared(smemp);
    asm volatile("cp.async.cg.shared.global [%0], [%1], 16;" :: "r"(s), "l"(gmem));
}
__device__ __forceinline__ void cp_commit() { asm volatile("cp.async.commit_group;"); }
__device__ __forceinline__ void cp_wait0()  { asm volatile("cp.async.wait_group 0;"); }

// ---- gather arithmetic: bit-exact bf16->f32 via shifts, packed f32x2 accumulate ----
__device__ __forceinline__ uint64_t pack_bf16x2_to_f32x2(uint32_t m) {
    uint32_t lo = m << 16;
    uint32_t hi = m & 0xFFFF0000u;
    uint64_t v;
    asm("mov.b64 %0, {%1,%2};" : "=l"(v) : "r"(lo), "r"(hi));
    return v;
}
__device__ __forceinline__ void acc_word(uint64_t& acc, uint32_t hw, uint32_t bw) {
    __nv_bfloat162 m = __hmax2(__hadd2(*(const __nv_bfloat162*)&hw,
                                       *(const __nv_bfloat162*)&bw),
                               __float2bfloat162_rn(0.f));
    uint64_t v = pack_bf16x2_to_f32x2(*(const uint32_t*)&m);
    asm("add.rn.f32x2 %0, %0, %1;" : "+l"(acc) : "l"(v));
}
__device__ __forceinline__ void acc_edge(uint64_t acc[4], uint4 h, uint4 b) {
    acc_word(acc[0], h.x, b.x);
    acc_word(acc[1], h.y, b.y);
    acc_word(acc[2], h.z, b.z);
    acc_word(acc[3], h.w, b.w);
}
__device__ __forceinline__ float2 unpack_f32x2(uint64_t v) {
    uint32_t lo, hi;
    asm("mov.b64 {%0,%1}, %2;" : "=r"(lo), "=r"(hi) : "l"(v));
    return make_float2(__uint_as_float(lo), __uint_as_float(hi));
}

// ---------------- mega setup ----------------
__global__ void mega_setup(
    const int* __restrict__ x, const float* __restrict__ atom,
    const float* __restrict__ be1, const float* __restrict__ be2,
    const float* __restrict__ w1, const float* __restrict__ w2,
    const float* __restrict__ w3, const float* __restrict__ w4,
    const int* __restrict__ ei, float* __restrict__ out) {
    int b = blockIdx.x;
    int t = threadIdx.x;
    if (b < 25000) {
        __shared__ int xi[4][9];
        if (t < 36) xi[t / 9][t % 9] = x[(b * 4 + t / 9) * 9 + (t % 9)];
        __syncthreads();
        int sub = t >> 6;
        int fg = (t & 63) * 4;
        size_t node = (size_t)b * 4 + sub;
        float4 s = make_float4(0.f, 0.f, 0.f, 0.f);
#pragma unroll
        for (int c = 0; c < 9; c++) {
            float4 v = *(const float4*)(atom + ((size_t)(c * 100 + xi[sub][c])) * DIM + fg);
            s.x += v.x; s.y += v.y; s.z += v.z; s.w += v.w;
        }
        uint2 packed;
        *(__nv_bfloat162*)&packed.x = __floats2bfloat162_rn(s.x, s.y);
        *(__nv_bfloat162*)&packed.y = __floats2bfloat162_rn(s.z, s.w);
        *(uint2*)(g_hb + node * DIM + fg) = packed;
    } else if (b < 27000) {
        int bb = b - 25000;
        const float* be = (bb < 1000) ? be1 : be2;
        int k = (bb < 1000) ? bb : bb - 1000;
        int a0 = k / 100, a1 = (k / 10) % 10, a2 = k % 10;
        float v = be[(size_t)(0 * 10 + a0) * DIM + t]
                + be[(size_t)(1 * 10 + a1) * DIM + t]
                + be[(size_t)(2 * 10 + a2) * DIM + t];
        g_bondb[(size_t)bb * DIM + t] = __float2bfloat16(v);
    } else if (b < 27512) {
        int i = (b - 27000) * 256 + t;
        ((float4*)out)[i] = make_float4(0.f, 0.f, 0.f, 0.f);
    } else if (b < 29048) {
        int i = (b - 27512) * 256 + t;
        const float* src;
        int off;
        if (i < 131072)      { src = w1; off = 0; }
        else if (i < 262144) { src = w2; off = 131072; }
        else if (i < 327680) { src = w3; off = 262144; }
        else                 { src = w4; off = 327680; }
        g_w[i] = to_tf32(src[i - off]);
    } else {
        int e = (b - 29048) * 256 + t;
        if (e < N_EDGESC) atomicAdd(&g_deg[__ldg(ei + N_EDGESC + e)], 1);
    }
}

// ---------------- scan offsets (+ zero stats) ----------------
__global__ void scan_offsets() {
    const int CH = 98;
    __shared__ int ssum[1024];
    int t = threadIdx.x;
    g_sum[t] = 0.f;
    g_sq[t] = 0.f;
    int base = t * CH;
    int local = 0;
    for (int i = 0; i < CH; i++) {
        int idx = base + i;
        if (idx <= N_NODESC) local += g_deg[idx];
    }
    ssum[t] = local;
    __syncthreads();
    for (int off = 1; off < 1024; off <<= 1) {
        int v = (t >= off) ? ssum[t - off] : 0;
        __syncthreads();
        if (t >= off) ssum[t] += v;
        __syncthreads();
    }
    int run = (t == 0) ? 0 : ssum[t - 1];
    for (int i = 0; i < CH; i++) {
        int idx = base + i;
        if (idx <= N_NODESC) {
            int d = g_deg[idx];
            g_off[idx] = run;
            if (idx < N_NODESC) g_pos[idx] = run;
            run += d;
        }
    }
}

// ---------------- fill CSR: byte offsets (+ re-zero deg) ----------------
__global__ void fill_csr(const int* __restrict__ ei, const int* __restrict__ ea) {
    int e = blockIdx.x * blockDim.x + threadIdx.x;
    if (e <= N_NODESC) g_deg[e] = 0;
    if (e >= N_EDGESC) return;
    int src = __ldg(ei + e);
    int dst = __ldg(ei + N_EDGESC + e);
    int key = __ldg(ea + (size_t)e * 3 + 0) * 100
            + __ldg(ea + (size_t)e * 3 + 1) * 10
            + __ldg(ea + (size_t)e * 3 + 2);
    int slot = atomicAdd(&g_pos[dst], 1);
    g_csr[slot] = make_int2(src << 9, key << 9);
}

// ---------------- gather (bf16x2 SIMD, f32x2 accumulate, unroll 4) ----------------
__global__ __launch_bounds__(256, 6) void gather_mp(const __nv_bfloat16* __restrict__ bond) {
    int n = (int)(((size_t)blockIdx.x * blockDim.x + threadIdx.x) >> 5);
    if (n >= N_NODESC) return;
    int lane = threadIdx.x & 31;
    unsigned fo2 = lane * 16;
    const char* hbase = (const char*)g_hb + fo2;
    const char* bbase = (const char*)bond + fo2;
    uint64_t acc[4];
    {
        uint4 hs = *(const uint4*)(hbase + ((unsigned)n << 9));
        acc[0] = pack_bf16x2_to_f32x2(hs.x);
        acc[1] = pack_bf16x2_to_f32x2(hs.y);
        acc[2] = pack_bf16x2_to_f32x2(hs.z);
        acc[3] = pack_bf16x2_to_f32x2(hs.w);
    }
    int p = g_off[n], pe = g_off[n + 1];
    if (p < pe && (p & 1)) {
        int2 sk = __ldg(&g_csr[p]);
        uint4 h = *(const uint4*)(hbase + (unsigned)sk.x);
        uint4 b = *(const uint4*)(bbase + (unsigned)sk.y);
        acc_edge(acc, h, b);
        p++;
    }
    for (; p + 4 <= pe; p += 4) {
        int4 e01 = *(const int4*)&g_csr[p];
        int4 e23 = *(const int4*)&g_csr[p + 2];
        uint4 h0 = *(const uint4*)(hbase + (unsigned)e01.x);
        uint4 b0 = *(const uint4*)(bbase + (unsigned)e01.y);
        uint4 h1 = *(const uint4*)(hbase + (unsigned)e01.z);
        uint4 b1 = *(const uint4*)(bbase + (unsigned)e01.w);
        uint4 h2 = *(const uint4*)(hbase + (unsigned)e23.x);
        uint4 b2 = *(const uint4*)(bbase + (unsigned)e23.y);
        uint4 h3 = *(const uint4*)(hbase + (unsigned)e23.z);
        uint4 b3 = *(const uint4*)(bbase + (unsigned)e23.w);
        acc_edge(acc, h0, b0);
        acc_edge(acc, h1, b1);
        acc_edge(acc, h2, b2);
        acc_edge(acc, h3, b3);
    }
    for (; p < pe; p++) {
        int2 sk = __ldg(&g_csr[p]);
        uint4 h = *(const uint4*)(hbase + (unsigned)sk.x);
        uint4 b = *(const uint4*)(bbase + (unsigned)sk.y);
        acc_edge(acc, h, b);
    }
    float2 r0 = unpack_f32x2(acc[0]);
    float2 r1 = unpack_f32x2(acc[1]);
    float2 r2 = unpack_f32x2(acc[2]);
    float2 r3 = unpack_f32x2(acc[3]);
    float* zd = g_z + (size_t)n * DIM + lane * 8;
    *(float4*)(zd)     = make_float4(r0.x, r0.y, r1.x, r1.y);
    *(float4*)(zd + 4) = make_float4(r2.x, r2.y, r3.x, r3.y);
}

// ---------------- BN finalize ----------------
__global__ void finstats(const float* __restrict__ gamma, const float* __restrict__ beta,
                         int Dh, int off) {
    int c = blockIdx.x * 256 + threadIdx.x;
    if (c >= Dh) return;
    float inv_n = 1.0f / (float)N_NODESC;
    float mu = g_sum[off + c] * inv_n;
    float var = g_sq[off + c] * inv_n - mu * mu;
    float rs = rsqrtf(var + EPSC);
    float sc = rs * gamma[c];
    g_scale[c] = sc;
    g_shift[c] = beta[c] - mu * sc;
}

// ---------------- tf32 tensor-core GEMM 128x128x16 (R12: padded, conflict-free) ----------------
template <bool TRANSFORM, bool RELU, int STATS, bool STOREC, bool BF16OUT, bool POOL>
__global__ __launch_bounds__(256) void gemm_tc(
    const float* __restrict__ A, const float* __restrict__ B,
    const float* __restrict__ bias, float* __restrict__ C,
    const int* __restrict__ batch, float* __restrict__ pool_out,
    int M, int K, int Nc) {
    const int BM = 128, BK = 16;
    const int BKP = BK + 4;
    const int BNP = 128 + 8;
    __shared__ float As[2][BM][BKP];
    __shared__ float Bs[2][BK][BNP];
    __shared__ int sbatch[BM];

    int tid = threadIdx.x;
    int lane = tid & 31;
    int wid = tid >> 5;
    int wm = wid & 1;
    int wn = wid >> 1;
    int bm = blockIdx.y * BM;
    int bn = blockIdx.x * 128;

    if (POOL && tid < BM) sbatch[tid] = (bm + tid < M) ? batch[bm + tid] : -1;

    int idx0 = tid, idx1 = tid + 256;
    int ar0 = idx0 >> 2, ak0 = (idx0 & 3) * 4;
    int ar1 = idx1 >> 2, ak1 = (idx1 & 3) * 4;
    int br0 = idx0 >> 5, bq0 = (idx0 & 31) * 4;
    int br1 = idx1 >> 5, bq1 = (idx1 & 31) * 4;
    bool aok0 = (bm + ar0) < M;
    bool aok1 = (bm + ar1) < M;

    float c[4][4][4];
#pragma unroll
    for (int mt = 0; mt < 4; mt++)
#pragma unroll
        for (int nt = 0; nt < 4; nt++)
#pragma unroll
            for (int r = 0; r < 4; r++) c[mt][nt][r] = 0.f;

    float4 a4s[2];

    auto ldg_a = [&](int k0) {
        a4s[0] = aok0 ? *(const float4*)(A + (size_t)(bm + ar0) * K + k0 + ak0)
                      : make_float4(0.f, 0.f, 0.f, 0.f);
        a4s[1] = aok1 ? *(const float4*)(A + (size_t)(bm + ar1) * K + k0 + ak1)
                      : make_float4(0.f, 0.f, 0.f, 0.f);
        if (TRANSFORM) {
#pragma unroll
            for (int t = 0; t < 2; t++) {
                int kb = k0 + ((t == 0) ? ak0 : ak1);
                float4& v = a4s[t];
                v.x = fmaxf(v.x * g_scale[kb + 0] + g_shift[kb + 0], 0.f);
                v.y = fmaxf(v.y * g_scale[kb + 1] + g_shift[kb + 1], 0.f);
                v.z = fmaxf(v.z * g_scale[kb + 2] + g_shift[kb + 2], 0.f);
                v.w = fmaxf(v.w * g_scale[kb + 3] + g_shift[kb + 3], 0.f);
            }
        }
    };
    auto sts_a = [&](int buf) {
        *(float4*)&As[buf][ar0][ak0] = make_float4(to_tf32(a4s[0].x), to_tf32(a4s[0].y),
                                                   to_tf32(a4s[0].z), to_tf32(a4s[0].w));
        *(float4*)&As[buf][ar1][ak1] = make_float4(to_tf32(a4s[1].x), to_tf32(a4s[1].y),
                                                   to_tf32(a4s[1].z), to_tf32(a4s[1].w));
    };
    auto ldb_async = [&](int buf, int k0) {
        cp_async16(&Bs[buf][br0][bq0], B + (size_t)(k0 + br0) * Nc + bn + bq0);
        cp_async16(&Bs[buf][br1][bq1], B + (size_t)(k0 + br1) * Nc + bn + bq1);
        cp_commit();
    };

    ldb_async(0, 0);
    ldg_a(0);
    sts_a(0);
    cp_wait0();
    __syncthreads();

    int nIter = K / BK;
    int lq = lane >> 2;
    int lr = lane & 3;
    for (int it = 0; it < nIter; it++) {
        int cur = it & 1, nxt = cur ^ 1;
        bool more = (it + 1 < nIter);
        if (more) {
            ldg_a((it + 1) * BK);
            ldb_async(nxt, (it + 1) * BK);
        }
#pragma unroll
        for (int ks = 0; ks < 2; ks++) {
            int k0 = ks * 8;
            uint32_t bf[4][2];
#pragma unroll
            for (int nt = 0; nt < 4; nt++) {
                int ncol = wn * 32 + nt * 8 + lq;
                bf[nt][0] = __float_as_uint(Bs[cur][k0 + lr][ncol]);
                bf[nt][1] = __float_as_uint(Bs[cur][k0 + 4 + lr][ncol]);
            }
#pragma unroll
            for (int mt = 0; mt < 4; mt++) {
                int mrow = wm * 64 + mt * 16 + lq;
                uint32_t af[4];
                af[0] = __float_as_uint(As[cur][mrow][k0 + lr]);
                af[1] = __float_as_uint(As[cur][mrow + 8][k0 + lr]);
                af[2] = __float_as_uint(As[cur][mrow][k0 + 4 + lr]);
                af[3] = __float_as_uint(As[cur][mrow + 8][k0 + 4 + lr]);
#pragma unroll
                for (int nt = 0; nt < 4; nt++) mma_tf32(c[mt][nt], af, bf[nt]);
            }
        }
        if (more) {
            sts_a(nxt);
            cp_wait0();
        }
        __syncthreads();
    }

    // ---------------- epilogue ----------------
    float2 bias2[4];
    int cbase[4];
#pragma unroll
    for (int nt = 0; nt < 4; nt++) {
        cbase[nt] = bn + wn * 32 + nt * 8 + lr * 2;
        bias2[nt] = *(const float2*)(bias + cbase[nt]);
    }

    float sx[4][2], qx[4][2];
    if (STATS >= 0) {
#pragma unroll
        for (int nt = 0; nt < 4; nt++) { sx[nt][0] = sx[nt][1] = 0.f; qx[nt][0] = qx[nt][1] = 0.f; }
    }

    float pl[4][2];
    int curb = -1;
    if (POOL) {
#pragma unroll
        for (int nt = 0; nt < 4; nt++) { pl[nt][0] = 0.f; pl[nt][1] = 0.f; }
    }

#pragma unroll
    for (int mt = 0; mt < 4; mt++) {
#pragma unroll
        for (int half = 0; half < 2; half++) {
            int rloc = wm * 64 + mt * 16 + lq + half * 8;
            int r = bm + rloc;
            if (r >= M) continue;
            float v[4][2];
#pragma unroll
            for (int nt = 0; nt < 4; nt++) {
                v[nt][0] = c[mt][nt][half * 2 + 0] + bias2[nt].x;
                v[nt][1] = c[mt][nt][half * 2 + 1] + bias2[nt].y;
                if (RELU) {
                    v[nt][0] = fmaxf(v[nt][0], 0.f);
                    v[nt][1] = fmaxf(v[nt][1], 0.f);
                }
                if (STATS >= 0) {
                    sx[nt][0] += v[nt][0]; sx[nt][1] += v[nt][1];
                    qx[nt][0] += v[nt][0] * v[nt][0]; qx[nt][1] += v[nt][1] * v[nt][1];
                }
            }
            if (STOREC) {
#pragma unroll
                for (int nt = 0; nt < 4; nt++)
                    *(float2*)(C + (size_t)r * Nc + cbase[nt]) = make_float2(v[nt][0], v[nt][1]);
            }
            if (BF16OUT) {
#pragma unroll
                for (int nt = 0; nt < 4; nt++)
                    *(__nv_bfloat162*)(g_hb + (size_t)r * DIM + cbase[nt]) =
                        __floats2bfloat162_rn(v[nt][0], v[nt][1]);
            }
            if (POOL) {
                int bg = sbatch[rloc];
                if (bg != curb) {
                    if (curb >= 0) {
#pragma unroll
                        for (int nt = 0; nt < 4; nt++) {
                            red_v2(pool_out + (size_t)curb * DIM + cbase[nt], pl[nt][0], pl[nt][1]);
                            pl[nt][0] = 0.f; pl[nt][1] = 0.f;
                        }
                    }
                    curb = bg;
                }
#pragma unroll
                for (int nt = 0; nt < 4; nt++) { pl[nt][0] += v[nt][0]; pl[nt][1] += v[nt][1]; }
            }
        }
    }
    if (POOL && curb >= 0) {
#pragma unroll
        for (int nt = 0; nt < 4; nt++)
            red_v2(pool_out + (size_t)curb * DIM + cbase[nt], pl[nt][0], pl[nt][1]);
    }

    if (STATS >= 0) {
#pragma unroll
        for (int nt = 0; nt < 4; nt++) {
#pragma unroll
            for (int h = 0; h < 2; h++) {
#pragma unroll
                for (int off = 4; off < 32; off <<= 1) {
                    sx[nt][h] += __shfl_xor_sync(0xffffffffu, sx[nt][h], off);
                    qx[nt][h] += __shfl_xor_sync(0xffffffffu, qx[nt][h], off);
                }
            }
        }
        if (lane < 4) {
#pragma unroll
            for (int nt = 0; nt < 4; nt++) {
                atomicAdd(&g_sum[STATS + cbase[nt] + 0], sx[nt][0]);
                atomicAdd(&g_sum[STATS + cbase[nt] + 1], sx[nt][1]);
                atomicAdd(&g_sq[STATS + cbase[nt] + 0], qx[nt][0]);
                atomicAdd(&g_sq[STATS + cbase[nt] + 1], qx[nt][1]);
            }
        }
    }
}

// ---------------- launch ----------------
extern "C" void kernel_launch(void* const* d_in, const int* in_sizes, int n_in,
                              void* d_out, int out_size) {
    const int* x      = (const int*)d_in[0];
    const int* ei     = (const int*)d_in[1];
    const int* ea     = (const int*)d_in[2];
    const int* batch  = (const int*)d_in[3];
    const float* atom = (const float*)d_in[4];
    const float* be1  = (const float*)d_in[5];
    const float* be2  = (const float*)d_in[6];
    const float* c1_w1 = (const float*)d_in[7];
    const float* c1_b1 = (const float*)d_in[8];
    const float* c1_g  = (const float*)d_in[9];
    const float* c1_be = (const float*)d_in[10];
    const float* c1_w2 = (const float*)d_in[11];
    const float* c1_b2 = (const float*)d_in[12];
    const float* c2_w1 = (const float*)d_in[13];
    const float* c2_b1 = (const float*)d_in[14];
    const float* c2_g  = (const float*)d_in[15];
    const float* c2_be = (const float*)d_in[16];
    const float* c2_w2 = (const float*)d_in[17];
    const float* c2_b2 = (const float*)d_in[18];
    float* out = (float*)d_out;

    float *zz, *yz, *wz;
    __nv_bfloat16 *bbz;
    cudaGetSymbolAddress((void**)&zz, g_z);
    cudaGetSymbolAddress((void**)&yz, g_y);
    cudaGetSymbolAddress((void**)&wz, g_w);
    cudaGetSymbolAddress((void**)&bbz, g_bondb);

    const int M = N_NODESC;
    const int eb = (N_EDGESC + 255) / 256;
    const int gb = (N_NODESC * 32 + 255) / 256;
    const int mtiles = (M + 127) / 128;
    dim3 gA(4, mtiles);   // Nc=512
    dim3 gB(2, mtiles);   // Nc=256

    // idx: mega(0) scan(1) fill(2) gather1(3) <- ncu samples idx 3
    mega_setup<<<41548, 256>>>(x, atom, be1, be2, c1_w1, c1_w2, c2_w1, c2_w2, ei, out);
    scan_offsets<<<1, 1024>>>();
    fill_csr<<<eb, 256>>>(ei, ea);

    // ---- conv1 ----
    gather_mp<<<gb, 256>>>(bbz);
    gemm_tc<false, false, 0, true, false, false><<<gA, 256>>>(zz, wz + 0, c1_b1, yz, nullptr, nullptr, M, 256, 512);
    finstats<<<2, 256>>>(c1_g, c1_be, 512, 0);
    gemm_tc<true, true, -1, false, true, false><<<gB, 256>>>(yz, wz + 131072, c1_b2, nullptr, nullptr, nullptr, M, 512, 256);

    // ---- conv2 ----
    gather_mp<<<gb, 256>>>(bbz + (size_t)1000 * DIM);
    gemm_tc<false, false, 512, true, false, false><<<gB, 256>>>(zz, wz + 262144, c2_b1, yz, nullptr, nullptr, M, 256, 256);
    finstats<<<1, 256>>>(c2_g, c2_be, 256, 512);
    gemm_tc<true, true, -1, false, false, true><<<gB, 256>>>(yz, wz + 327680, c2_b2, nullptr, batch, out, M, 256, 256);
}

// round 16
// speedup vs baseline: 1.2834x; 1.1795x over previous
#include <cuda_runtime.h>
#include <cuda_bf16.h>
#include <cstddef>
#include <cstdint>

#define N_NODESC 100000
#define N_EDGESC 3200000
#define N_GRAPHSC 2048
#define DIM 256
#define EPSC 1e-5f

// ---------------- scratch ----------------
__device__ float g_z[(size_t)N_NODESC * DIM];
__device__ float g_y[(size_t)N_NODESC * 2 * DIM];
__device__ __nv_bfloat16 g_hb[(size_t)N_NODESC * DIM];   // bf16 node features
__device__ __nv_bfloat16 g_bondb[2000 * DIM];            // bf16 combined bond tables
__device__ float g_w[393216];            // tf32-rounded weights (linear): w1|w2|w3|w4
__device__ int   g_deg[N_NODESC + 1];
__device__ int   g_off[N_NODESC + 1];
__device__ int   g_pos[N_NODESC];
__device__ int   g_bsum[128];            // block partial sums for parallel scan
__device__ __align__(16) int2 g_csr[N_EDGESC];           // (src*512, key*512) byte offsets
__device__ float g_sum[1024];
__device__ float g_sq[1024];
__device__ float g_scale[512];
__device__ float g_shift[512];

__device__ __forceinline__ void red_v2(float* addr, float a, float b) {
    asm volatile("red.global.add.v2.f32 [%0], {%1,%2};"
                 :: "l"(addr), "f"(a), "f"(b) : "memory");
}
__device__ __forceinline__ float to_tf32(float x) {
    uint32_t r;
    asm("cvt.rna.tf32.f32 %0, %1;" : "=r"(r) : "f"(x));
    return __uint_as_float(r);
}
__device__ __forceinline__ void mma_tf32(float c[4], const uint32_t a[4], const uint32_t b[2]) {
    asm volatile(
        "mma.sync.aligned.m16n8k8.row.col.f32.tf32.tf32.f32 "
        "{%0,%1,%2,%3}, {%4,%5,%6,%7}, {%8,%9}, {%0,%1,%2,%3};"
        : "+f"(c[0]), "+f"(c[1]), "+f"(c[2]), "+f"(c[3])
        : "r"(a[0]), "r"(a[1]), "r"(a[2]), "r"(a[3]), "r"(b[0]), "r"(b[1]));
}
__device__ __forceinline__ void cp_async16(void* smemp, const void* gmem) {
    unsigned s = (unsigned)__cvta_generic_to_shared(smemp);
    asm volatile("cp.async.cg.shared.global [%0], [%1], 16;" :: "r"(s), "l"(gmem));
}
__device__ __forceinline__ void cp_commit() { asm volatile("cp.async.commit_group;"); }
__device__ __forceinline__ void cp_wait0()  { asm volatile("cp.async.wait_group 0;"); }

// ---- gather arithmetic: bit-exact bf16->f32 via shifts, packed f32x2 accumulate ----
__device__ __forceinline__ uint64_t pack_bf16x2_to_f32x2(uint32_t m) {
    uint32_t lo = m << 16;
    uint32_t hi = m & 0xFFFF0000u;
    uint64_t v;
    asm("mov.b64 %0, {%1,%2};" : "=l"(v) : "r"(lo), "r"(hi));
    return v;
}
__device__ __forceinline__ void acc_word(uint64_t& acc, uint32_t hw, uint32_t bw) {
    __nv_bfloat162 m = __hmax2(__hadd2(*(const __nv_bfloat162*)&hw,
                                       *(const __nv_bfloat162*)&bw),
                               __float2bfloat162_rn(0.f));
    uint64_t v = pack_bf16x2_to_f32x2(*(const uint32_t*)&m);
    asm("add.rn.f32x2 %0, %0, %1;" : "+l"(acc) : "l"(v));
}
__device__ __forceinline__ void acc_edge(uint64_t acc[4], uint4 h, uint4 b) {
    acc_word(acc[0], h.x, b.x);
    acc_word(acc[1], h.y, b.y);
    acc_word(acc[2], h.z, b.z);
    acc_word(acc[3], h.w, b.w);
}
__device__ __forceinline__ float2 unpack_f32x2(uint64_t v) {
    uint32_t lo, hi;
    asm("mov.b64 {%0,%1}, %2;" : "=r"(lo), "=r"(hi) : "l"(v));
    return make_float2(__uint_as_float(lo), __uint_as_float(hi));
}

// ---------------- mega setup ----------------
__global__ void mega_setup(
    const int* __restrict__ x, const float* __restrict__ atom,
    const float* __restrict__ be1, const float* __restrict__ be2,
    const float* __restrict__ w1, const float* __restrict__ w2,
    const float* __restrict__ w3, const float* __restrict__ w4,
    const int* __restrict__ ei, float* __restrict__ out) {
    int b = blockIdx.x;
    int t = threadIdx.x;
    if (b < 25000) {
        __shared__ int xi[4][9];
        if (t < 36) xi[t / 9][t % 9] = x[(b * 4 + t / 9) * 9 + (t % 9)];
        __syncthreads();
        int sub = t >> 6;
        int fg = (t & 63) * 4;
        size_t node = (size_t)b * 4 + sub;
        float4 s = make_float4(0.f, 0.f, 0.f, 0.f);
#pragma unroll
        for (int c = 0; c < 9; c++) {
            float4 v = *(const float4*)(atom + ((size_t)(c * 100 + xi[sub][c])) * DIM + fg);
            s.x += v.x; s.y += v.y; s.z += v.z; s.w += v.w;
        }
        uint2 packed;
        *(__nv_bfloat162*)&packed.x = __floats2bfloat162_rn(s.x, s.y);
        *(__nv_bfloat162*)&packed.y = __floats2bfloat162_rn(s.z, s.w);
        *(uint2*)(g_hb + node * DIM + fg) = packed;
    } else if (b < 27000) {
        int bb = b - 25000;
        const float* be = (bb < 1000) ? be1 : be2;
        int k = (bb < 1000) ? bb : bb - 1000;
        int a0 = k / 100, a1 = (k / 10) % 10, a2 = k % 10;
        float v = be[(size_t)(0 * 10 + a0) * DIM + t]
                + be[(size_t)(1 * 10 + a1) * DIM + t]
                + be[(size_t)(2 * 10 + a2) * DIM + t];
        g_bondb[(size_t)bb * DIM + t] = __float2bfloat16(v);
    } else if (b < 27512) {
        int i = (b - 27000) * 256 + t;
        ((float4*)out)[i] = make_float4(0.f, 0.f, 0.f, 0.f);
    } else if (b < 29048) {
        int i = (b - 27512) * 256 + t;
        const float* src;
        int off;
        if (i < 131072)      { src = w1; off = 0; }
        else if (i < 262144) { src = w2; off = 131072; }
        else if (i < 327680) { src = w3; off = 262144; }
        else                 { src = w4; off = 327680; }
        g_w[i] = to_tf32(src[i - off]);
    } else {
        int e = (b - 29048) * 256 + t;
        if (e < N_EDGESC) atomicAdd(&g_deg[__ldg(ei + N_EDGESC + e)], 1);
    }
}

// ---------------- parallel scan: 3 phases ----------------
// phase 1: 99 blocks x 1024 threads reduce their 1024-element chunk of g_deg
__global__ void scan_reduce() {
    __shared__ int ssum[1024];
    int t = threadIdx.x;
    int idx = blockIdx.x * 1024 + t;
    int v = (idx <= N_NODESC) ? g_deg[idx] : 0;
    ssum[t] = v;
    __syncthreads();
    for (int off = 512; off > 0; off >>= 1) {
        if (t < off) ssum[t] += ssum[t + off];
        __syncthreads();
    }
    if (t == 0) g_bsum[blockIdx.x] = ssum[0];
}
// phase 2: exclusive scan of 99 block sums + zero stats (1 block)
__global__ void scan_blocks() {
    __shared__ int ss[128];
    int t = threadIdx.x;
    g_sum[t] = 0.f;
    g_sq[t] = 0.f;
    g_sum[512 + t] = 0.f;
    g_sq[512 + t] = 0.f;
    ss[t % 128] = 0;      // will be overwritten below for t<128
    __syncthreads();
    if (t < 128) ss[t] = (t < 99) ? g_bsum[t] : 0;
    __syncthreads();
    if (t < 128) {
        for (int off = 1; off < 128; off <<= 1) {
            int v = (t >= off) ? ss[t - off] : 0;
            __syncthreads();
            if (t >= off) ss[t] += v;
            __syncthreads();
        }
        g_bsum[t] = (t == 0) ? 0 : ss[t - 1];   // exclusive
    }
}
// phase 3: 99 blocks local scan + base, write g_off/g_pos
__global__ void scan_expand() {
    __shared__ int ss[1024];
    int t = threadIdx.x;
    int idx = blockIdx.x * 1024 + t;
    int v = (idx <= N_NODESC) ? g_deg[idx] : 0;
    ss[t] = v;
    __syncthreads();
    // inclusive scan
    for (int off = 1; off < 1024; off <<= 1) {
        int u = (t >= off) ? ss[t - off] : 0;
        __syncthreads();
        if (t >= off) ss[t] += u;
        __syncthreads();
    }
    if (idx <= N_NODESC) {
        int base = g_bsum[blockIdx.x];
        int excl = base + ss[t] - v;            // exclusive prefix
        g_off[idx] = excl;
        if (idx < N_NODESC) g_pos[idx] = excl;
    }
}

// ---------------- fill CSR: byte offsets (+ re-zero deg) ----------------
__global__ void fill_csr(const int* __restrict__ ei, const int* __restrict__ ea) {
    int e = blockIdx.x * blockDim.x + threadIdx.x;
    if (e <= N_NODESC) g_deg[e] = 0;
    if (e >= N_EDGESC) return;
    int src = __ldg(ei + e);
    int dst = __ldg(ei + N_EDGESC + e);
    int key = __ldg(ea + (size_t)e * 3 + 0) * 100
            + __ldg(ea + (size_t)e * 3 + 1) * 10
            + __ldg(ea + (size_t)e * 3 + 2);
    int slot = atomicAdd(&g_pos[dst], 1);
    g_csr[slot] = make_int2(src << 9, key << 9);
}

// ---------------- gather (bf16x2 SIMD, f32x2 accumulate, unroll 4) ----------------
__global__ __launch_bounds__(256, 6) void gather_mp(const __nv_bfloat16* __restrict__ bond) {
    int n = (int)(((size_t)blockIdx.x * blockDim.x + threadIdx.x) >> 5);
    if (n >= N_NODESC) return;
    int lane = threadIdx.x & 31;
    unsigned fo2 = lane * 16;
    const char* hbase = (const char*)g_hb + fo2;
    const char* bbase = (const char*)bond + fo2;
    uint64_t acc[4];
    {
        uint4 hs = *(const uint4*)(hbase + ((unsigned)n << 9));
        acc[0] = pack_bf16x2_to_f32x2(hs.x);
        acc[1] = pack_bf16x2_to_f32x2(hs.y);
        acc[2] = pack_bf16x2_to_f32x2(hs.z);
        acc[3] = pack_bf16x2_to_f32x2(hs.w);
    }
    int p = g_off[n], pe = g_off[n + 1];
    if (p < pe && (p & 1)) {
        int2 sk = __ldg(&g_csr[p]);
        uint4 h = *(const uint4*)(hbase + (unsigned)sk.x);
        uint4 b = *(const uint4*)(bbase + (unsigned)sk.y);
        acc_edge(acc, h, b);
        p++;
    }
    for (; p + 4 <= pe; p += 4) {
        int4 e01 = *(const int4*)&g_csr[p];
        int4 e23 = *(const int4*)&g_csr[p + 2];
        uint4 h0 = *(const uint4*)(hbase + (unsigned)e01.x);
        uint4 b0 = *(const uint4*)(bbase + (unsigned)e01.y);
        uint4 h1 = *(const uint4*)(hbase + (unsigned)e01.z);
        uint4 b1 = *(const uint4*)(bbase + (unsigned)e01.w);
        uint4 h2 = *(const uint4*)(hbase + (unsigned)e23.x);
        uint4 b2 = *(const uint4*)(bbase + (unsigned)e23.y);
        uint4 h3 = *(const uint4*)(hbase + (unsigned)e23.z);
        uint4 b3 = *(const uint4*)(bbase + (unsigned)e23.w);
        acc_edge(acc, h0, b0);
        acc_edge(acc, h1, b1);
        acc_edge(acc, h2, b2);
        acc_edge(acc, h3, b3);
    }
    for (; p < pe; p++) {
        int2 sk = __ldg(&g_csr[p]);
        uint4 h = *(const uint4*)(hbase + (unsigned)sk.x);
        uint4 b = *(const uint4*)(bbase + (unsigned)sk.y);
        acc_edge(acc, h, b);
    }
    float2 r0 = unpack_f32x2(acc[0]);
    float2 r1 = unpack_f32x2(acc[1]);
    float2 r2 = unpack_f32x2(acc[2]);
    float2 r3 = unpack_f32x2(acc[3]);
    float* zd = g_z + (size_t)n * DIM + lane * 8;
    *(float4*)(zd)     = make_float4(r0.x, r0.y, r1.x, r1.y);
    *(float4*)(zd + 4) = make_float4(r2.x, r2.y, r3.x, r3.y);
}

// ---------------- BN finalize ----------------
__global__ void finstats(const float* __restrict__ gamma, const float* __restrict__ beta,
                         int Dh, int off) {
    int c = blockIdx.x * 256 + threadIdx.x;
    if (c >= Dh) return;
    float inv_n = 1.0f / (float)N_NODESC;
    float mu = g_sum[off + c] * inv_n;
    float var = g_sq[off + c] * inv_n - mu * mu;
    float rs = rsqrtf(var + EPSC);
    float sc = rs * gamma[c];
    g_scale[c] = sc;
    g_shift[c] = beta[c] - mu * sc;
}

// ---------------- tf32 tensor-core GEMM 128x128x16 (padded, conflict-free, 2 CTAs/SM) ----------------
template <bool TRANSFORM, bool RELU, int STATS, bool STOREC, bool BF16OUT, bool POOL>
__global__ __launch_bounds__(256, 2) void gemm_tc(
    const float* __restrict__ A, const float* __restrict__ B,
    const float* __restrict__ bias, float* __restrict__ C,
    const int* __restrict__ batch, float* __restrict__ pool_out,
    int M, int K, int Nc) {
    const int BM = 128, BK = 16;
    const int BKP = BK + 4;
    const int BNP = 128 + 8;
    __shared__ float As[2][BM][BKP];
    __shared__ float Bs[2][BK][BNP];
    __shared__ int sbatch[BM];

    int tid = threadIdx.x;
    int lane = tid & 31;
    int wid = tid >> 5;
    int wm = wid & 1;
    int wn = wid >> 1;
    int bm = blockIdx.y * BM;
    int bn = blockIdx.x * 128;

    if (POOL && tid < BM) sbatch[tid] = (bm + tid < M) ? batch[bm + tid] : -1;

    int idx0 = tid, idx1 = tid + 256;
    int ar0 = idx0 >> 2, ak0 = (idx0 & 3) * 4;
    int ar1 = idx1 >> 2, ak1 = (idx1 & 3) * 4;
    int br0 = idx0 >> 5, bq0 = (idx0 & 31) * 4;
    int br1 = idx1 >> 5, bq1 = (idx1 & 31) * 4;
    bool aok0 = (bm + ar0) < M;
    bool aok1 = (bm + ar1) < M;

    float c[4][4][4];
#pragma unroll
    for (int mt = 0; mt < 4; mt++)
#pragma unroll
        for (int nt = 0; nt < 4; nt++)
#pragma unroll
            for (int r = 0; r < 4; r++) c[mt][nt][r] = 0.f;

    float4 a4s[2];

    auto ldg_a = [&](int k0) {
        a4s[0] = aok0 ? *(const float4*)(A + (size_t)(bm + ar0) * K + k0 + ak0)
                      : make_float4(0.f, 0.f, 0.f, 0.f);
        a4s[1] = aok1 ? *(const float4*)(A + (size_t)(bm + ar1) * K + k0 + ak1)
                      : make_float4(0.f, 0.f, 0.f, 0.f);
        if (TRANSFORM) {
#pragma unroll
            for (int t = 0; t < 2; t++) {
                int kb = k0 + ((t == 0) ? ak0 : ak1);
                float4& v = a4s[t];
                v.x = fmaxf(v.x * g_scale[kb + 0] + g_shift[kb + 0], 0.f);
                v.y = fmaxf(v.y * g_scale[kb + 1] + g_shift[kb + 1], 0.f);
                v.z = fmaxf(v.z * g_scale[kb + 2] + g_shift[kb + 2], 0.f);
                v.w = fmaxf(v.w * g_scale[kb + 3] + g_shift[kb + 3], 0.f);
            }
        }
    };
    auto sts_a = [&](int buf) {
        *(float4*)&As[buf][ar0][ak0] = make_float4(to_tf32(a4s[0].x), to_tf32(a4s[0].y),
                                                   to_tf32(a4s[0].z), to_tf32(a4s[0].w));
        *(float4*)&As[buf][ar1][ak1] = make_float4(to_tf32(a4s[1].x), to_tf32(a4s[1].y),
                                                   to_tf32(a4s[1].z), to_tf32(a4s[1].w));
    };
    auto ldb_async = [&](int buf, int k0) {
        cp_async16(&Bs[buf][br0][bq0], B + (size_t)(k0 + br0) * Nc + bn + bq0);
        cp_async16(&Bs[buf][br1][bq1], B + (size_t)(k0 + br1) * Nc + bn + bq1);
        cp_commit();
    };

    ldb_async(0, 0);
    ldg_a(0);
    sts_a(0);
    cp_wait0();
    __syncthreads();

    int nIter = K / BK;
    int lq = lane >> 2;
    int lr = lane & 3;
    for (int it = 0; it < nIter; it++) {
        int cur = it & 1, nxt = cur ^ 1;
        bool more = (it + 1 < nIter);
        if (more) {
            ldg_a((it + 1) * BK);
            ldb_async(nxt, (it + 1) * BK);
        }
#pragma unroll
        for (int ks = 0; ks < 2; ks++) {
            int k0 = ks * 8;
            uint32_t bf[4][2];
#pragma unroll
            for (int nt = 0; nt < 4; nt++) {
                int ncol = wn * 32 + nt * 8 + lq;
                bf[nt][0] = __float_as_uint(Bs[cur][k0 + lr][ncol]);
                bf[nt][1] = __float_as_uint(Bs[cur][k0 + 4 + lr][ncol]);
            }
#pragma unroll
            for (int mt = 0; mt < 4; mt++) {
                int mrow = wm * 64 + mt * 16 + lq;
                uint32_t af[4];
                af[0] = __float_as_uint(As[cur][mrow][k0 + lr]);
                af[1] = __float_as_uint(As[cur][mrow + 8][k0 + lr]);
                af[2] = __float_as_uint(As[cur][mrow][k0 + 4 + lr]);
                af[3] = __float_as_uint(As[cur][mrow + 8][k0 + 4 + lr]);
#pragma unroll
                for (int nt = 0; nt < 4; nt++) mma_tf32(c[mt][nt], af, bf[nt]);
            }
        }
        if (more) {
            sts_a(nxt);
            cp_wait0();
        }
        __syncthreads();
    }

    // ---------------- epilogue ----------------
    float2 bias2[4];
    int cbase[4];
#pragma unroll
    for (int nt = 0; nt < 4; nt++) {
        cbase[nt] = bn + wn * 32 + nt * 8 + lr * 2;
        bias2[nt] = *(const float2*)(bias + cbase[nt]);
    }

    float sx[4][2], qx[4][2];
    if (STATS >= 0) {
#pragma unroll
        for (int nt = 0; nt < 4; nt++) { sx[nt][0] = sx[nt][1] = 0.f; qx[nt][0] = qx[nt][1] = 0.f; }
    }

    float pl[4][2];
    int curb = -1;
    if (POOL) {
#pragma unroll
        for (int nt = 0; nt < 4; nt++) { pl[nt][0] = 0.f; pl[nt][1] = 0.f; }
    }

#pragma unroll
    for (int mt = 0; mt < 4; mt++) {
#pragma unroll
        for (int half = 0; half < 2; half++) {
            int rloc = wm * 64 + mt * 16 + lq + half * 8;
            int r = bm + rloc;
            if (r >= M) continue;
            float v[4][2];
#pragma unroll
            for (int nt = 0; nt < 4; nt++) {
                v[nt][0] = c[mt][nt][half * 2 + 0] + bias2[nt].x;
                v[nt][1] = c[mt][nt][half * 2 + 1] + bias2[nt].y;
                if (RELU) {
                    v[nt][0] = fmaxf(v[nt][0], 0.f);
                    v[nt][1] = fmaxf(v[nt][1], 0.f);
                }
                if (STATS >= 0) {
                    sx[nt][0] += v[nt][0]; sx[nt][1] += v[nt][1];
                    qx[nt][0] += v[nt][0] * v[nt][0]; qx[nt][1] += v[nt][1] * v[nt][1];
                }
            }
            if (STOREC) {
#pragma unroll
                for (int nt = 0; nt < 4; nt++)
                    *(float2*)(C + (size_t)r * Nc + cbase[nt]) = make_float2(v[nt][0], v[nt][1]);
            }
            if (BF16OUT) {
#pragma unroll
                for (int nt = 0; nt < 4; nt++)
                    *(__nv_bfloat162*)(g_hb + (size_t)r * DIM + cbase[nt]) =
                        __floats2bfloat162_rn(v[nt][0], v[nt][1]);
            }
            if (POOL) {
                int bg = sbatch[rloc];
                if (bg != curb) {
                    if (curb >= 0) {
#pragma unroll
                        for (int nt = 0; nt < 4; nt++) {
                            red_v2(pool_out + (size_t)curb * DIM + cbase[nt], pl[nt][0], pl[nt][1]);
                            pl[nt][0] = 0.f; pl[nt][1] = 0.f;
                        }
                    }
                    curb = bg;
                }
#pragma unroll
                for (int nt = 0; nt < 4; nt++) { pl[nt][0] += v[nt][0]; pl[nt][1] += v[nt][1]; }
            }
        }
    }
    if (POOL && curb >= 0) {
#pragma unroll
        for (int nt = 0; nt < 4; nt++)
            red_v2(pool_out + (size_t)curb * DIM + cbase[nt], pl[nt][0], pl[nt][1]);
    }

    if (STATS >= 0) {
#pragma unroll
        for (int nt = 0; nt < 4; nt++) {
#pragma unroll
            for (int h = 0; h < 2; h++) {
#pragma unroll
                for (int off = 4; off < 32; off <<= 1) {
                    sx[nt][h] += __shfl_xor_sync(0xffffffffu, sx[nt][h], off);
                    qx[nt][h] += __shfl_xor_sync(0xffffffffu, qx[nt][h], off);
                }
            }
        }
        if (lane < 4) {
#pragma unroll
            for (int nt = 0; nt < 4; nt++) {
                atomicAdd(&g_sum[STATS + cbase[nt] + 0], sx[nt][0]);
                atomicAdd(&g_sum[STATS + cbase[nt] + 1], sx[nt][1]);
                atomicAdd(&g_sq[STATS + cbase[nt] + 0], qx[nt][0]);
                atomicAdd(&g_sq[STATS + cbase[nt] + 1], qx[nt][1]);
            }
        }
    }
}

// ---------------- launch ----------------
extern "C" void kernel_launch(void* const* d_in, const int* in_sizes, int n_in,
                              void* d_out, int out_size) {
    const int* x      = (const int*)d_in[0];
    const int* ei     = (const int*)d_in[1];
    const int* ea     = (const int*)d_in[2];
    const int* batch  = (const int*)d_in[3];
    const float* atom = (const float*)d_in[4];
    const float* be1  = (const float*)d_in[5];
    const float* be2  = (const float*)d_in[6];
    const float* c1_w1 = (const float*)d_in[7];
    const float* c1_b1 = (const float*)d_in[8];
    const float* c1_g  = (const float*)d_in[9];
    const float* c1_be = (const float*)d_in[10];
    const float* c1_w2 = (const float*)d_in[11];
    const float* c1_b2 = (const float*)d_in[12];
    const float* c2_w1 = (const float*)d_in[13];
    const float* c2_b1 = (const float*)d_in[14];
    const float* c2_g  = (const float*)d_in[15];
    const float* c2_be = (const float*)d_in[16];
    const float* c2_w2 = (const float*)d_in[17];
    const float* c2_b2 = (const float*)d_in[18];
    float* out = (float*)d_out;

    float *zz, *yz, *wz;
    __nv_bfloat16 *bbz;
    cudaGetSymbolAddress((void**)&zz, g_z);
    cudaGetSymbolAddress((void**)&yz, g_y);
    cudaGetSymbolAddress((void**)&wz, g_w);
    cudaGetSymbolAddress((void**)&bbz, g_bondb);

    const int M = N_NODESC;
    const int eb = (N_EDGESC + 255) / 256;
    const int gb = (N_NODESC * 32 + 255) / 256;
    const int mtiles = (M + 127) / 128;
    dim3 gA(4, mtiles);   // Nc=512
    dim3 gB(2, mtiles);   // Nc=256
    const int sblocks = (N_NODESC + 1 + 1023) / 1024;   // 99

    // idx: mega(0) red(1) blk(2) exp(3) fill(4) gather1(5) ...
    mega_setup<<<41548, 256>>>(x, atom, be1, be2, c1_w1, c1_w2, c2_w1, c2_w2, ei, out);
    scan_reduce<<<sblocks, 1024>>>();
    scan_blocks<<<1, 512>>>();
    scan_expand<<<sblocks, 1024>>>();
    fill_csr<<<eb, 256>>>(ei, ea);

    // ---- conv1 ----
    gather_mp<<<gb, 256>>>(bbz);
    gemm_tc<false, false, 0, true, false, false><<<gA, 256>>>(zz, wz + 0, c1_b1, yz, nullptr, nullptr, M, 256, 512);
    finstats<<<2, 256>>>(c1_g, c1_be, 512, 0);
    gemm_tc<true, true, -1, false, true, false><<<gB, 256>>>(yz, wz + 131072, c1_b2, nullptr, nullptr, nullptr, M, 512, 256);

    // ---- conv2 ----
    gather_mp<<<gb, 256>>>(bbz + (size_t)1000 * DIM);
    gemm_tc<false, false, 512, true, false, false><<<gB, 256>>>(zz, wz + 262144, c2_b1, yz, nullptr, nullptr, M, 256, 256);
    finstats<<<1, 256>>>(c2_g, c2_be, 256, 512);
    gemm_tc<true, true, -1, false, false, true><<<gB, 256>>>(yz, wz + 327680, c2_b2, nullptr, batch, out, M, 256, 256);
}

// round 17
// speedup vs baseline: 1.2930x; 1.0075x over previous
#include <cuda_runtime.h>
#include <cuda_bf16.h>
#include <cstddef>
#include <cstdint>

#define N_NODESC 100000
#define N_EDGESC 3200000
#define N_GRAPHSC 2048
#define DIM 256
#define EPSC 1e-5f

// ---------------- scratch ----------------
__device__ float g_z[(size_t)N_NODESC * DIM];
__device__ float g_y[(size_t)N_NODESC * 2 * DIM];
__device__ __nv_bfloat16 g_hb[(size_t)N_NODESC * DIM];   // bf16 node features
__device__ __nv_bfloat16 g_bondb[2000 * DIM];            // bf16 combined bond tables
__device__ float g_w[393216];            // tf32-rounded weights (linear): w1|w2|w3|w4
__device__ int   g_deg[N_NODESC + 1];
__device__ int   g_off[N_NODESC + 1];
__device__ int   g_pos[N_NODESC];
__device__ int   g_bsum[128];
__device__ __align__(16) int2 g_csr[N_EDGESC];           // (src*512, key*512) byte offsets
__device__ float g_sum[1024];
__device__ float g_sq[1024];
__device__ float g_scale[512];
__device__ float g_shift[512];

__device__ __forceinline__ void red_v2(float* addr, float a, float b) {
    asm volatile("red.global.add.v2.f32 [%0], {%1,%2};"
                 :: "l"(addr), "f"(a), "f"(b) : "memory");
}
__device__ __forceinline__ float to_tf32(float x) {
    uint32_t r;
    asm("cvt.rna.tf32.f32 %0, %1;" : "=r"(r) : "f"(x));
    return __uint_as_float(r);
}
__device__ __forceinline__ void mma_tf32(float c[4], const uint32_t a[4], const uint32_t b[2]) {
    asm volatile(
        "mma.sync.aligned.m16n8k8.row.col.f32.tf32.tf32.f32 "
        "{%0,%1,%2,%3}, {%4,%5,%6,%7}, {%8,%9}, {%0,%1,%2,%3};"
        : "+f"(c[0]), "+f"(c[1]), "+f"(c[2]), "+f"(c[3])
        : "r"(a[0]), "r"(a[1]), "r"(a[2]), "r"(a[3]), "r"(b[0]), "r"(b[1]));
}
__device__ __forceinline__ void cp_async16(void* smemp, const void* gmem) {
    unsigned s = (unsigned)__cvta_generic_to_shared(smemp);
    asm volatile("cp.async.cg.shared.global [%0], [%1], 16;" :: "r"(s), "l"(gmem));
}
__device__ __forceinline__ void cp_commit() { asm volatile("cp.async.commit_group;"); }
__device__ __forceinline__ void cp_wait0()  { asm volatile("cp.async.wait_group 0;"); }

// ---- gather arithmetic: bit-exact bf16->f32 via shifts, packed f32x2 accumulate ----
__device__ __forceinline__ uint64_t pack_bf16x2_to_f32x2(uint32_t m) {
    uint32_t lo = m << 16;
    uint32_t hi = m & 0xFFFF0000u;
    uint64_t v;
    asm("mov.b64 %0, {%1,%2};" : "=l"(v) : "r"(lo), "r"(hi));
    return v;
}
__device__ __forceinline__ void acc_word(uint64_t& acc, uint32_t hw, uint32_t bw) {
    __nv_bfloat162 m = __hmax2(__hadd2(*(const __nv_bfloat162*)&hw,
                                       *(const __nv_bfloat162*)&bw),
                               __float2bfloat162_rn(0.f));
    uint64_t v = pack_bf16x2_to_f32x2(*(const uint32_t*)&m);
    asm("add.rn.f32x2 %0, %0, %1;" : "+l"(acc) : "l"(v));
}
__device__ __forceinline__ void acc_edge(uint64_t acc[4], uint4 h, uint4 b) {
    acc_word(acc[0], h.x, b.x);
    acc_word(acc[1], h.y, b.y);
    acc_word(acc[2], h.z, b.z);
    acc_word(acc[3], h.w, b.w);
}
__device__ __forceinline__ float2 unpack_f32x2_tf32(uint64_t v) {
    uint32_t lo, hi;
    asm("mov.b64 {%0,%1}, %2;" : "=r"(lo), "=r"(hi) : "l"(v));
    return make_float2(to_tf32(__uint_as_float(lo)), to_tf32(__uint_as_float(hi)));
}

// ---------------- mega setup ----------------
__global__ void mega_setup(
    const int* __restrict__ x, const float* __restrict__ atom,
    const float* __restrict__ be1, const float* __restrict__ be2,
    const float* __restrict__ w1, const float* __restrict__ w2,
    const float* __restrict__ w3, const float* __restrict__ w4,
    const int* __restrict__ ei, float* __restrict__ out) {
    int b = blockIdx.x;
    int t = threadIdx.x;
    if (b < 25000) {
        __shared__ int xi[4][9];
        if (t < 36) xi[t / 9][t % 9] = x[(b * 4 + t / 9) * 9 + (t % 9)];
        __syncthreads();
        int sub = t >> 6;
        int fg = (t & 63) * 4;
        size_t node = (size_t)b * 4 + sub;
        float4 s = make_float4(0.f, 0.f, 0.f, 0.f);
#pragma unroll
        for (int c = 0; c < 9; c++) {
            float4 v = *(const float4*)(atom + ((size_t)(c * 100 + xi[sub][c])) * DIM + fg);
            s.x += v.x; s.y += v.y; s.z += v.z; s.w += v.w;
        }
        uint2 packed;
        *(__nv_bfloat162*)&packed.x = __floats2bfloat162_rn(s.x, s.y);
        *(__nv_bfloat162*)&packed.y = __floats2bfloat162_rn(s.z, s.w);
        *(uint2*)(g_hb + node * DIM + fg) = packed;
    } else if (b < 27000) {
        int bb = b - 25000;
        const float* be = (bb < 1000) ? be1 : be2;
        int k = (bb < 1000) ? bb : bb - 1000;
        int a0 = k / 100, a1 = (k / 10) % 10, a2 = k % 10;
        float v = be[(size_t)(0 * 10 + a0) * DIM + t]
                + be[(size_t)(1 * 10 + a1) * DIM + t]
                + be[(size_t)(2 * 10 + a2) * DIM + t];
        g_bondb[(size_t)bb * DIM + t] = __float2bfloat16(v);
    } else if (b < 27512) {
        int i = (b - 27000) * 256 + t;
        ((float4*)out)[i] = make_float4(0.f, 0.f, 0.f, 0.f);
    } else if (b < 29048) {
        int i = (b - 27512) * 256 + t;
        const float* src;
        int off;
        if (i < 131072)      { src = w1; off = 0; }
        else if (i < 262144) { src = w2; off = 131072; }
        else if (i < 327680) { src = w3; off = 262144; }
        else                 { src = w4; off = 327680; }
        g_w[i] = to_tf32(src[i - off]);
    } else {
        int e = (b - 29048) * 256 + t;
        if (e < N_EDGESC) atomicAdd(&g_deg[__ldg(ei + N_EDGESC + e)], 1);
    }
}

// ---------------- parallel scan: 3 phases ----------------
__global__ void scan_reduce() {
    __shared__ int ssum[1024];
    int t = threadIdx.x;
    int idx = blockIdx.x * 1024 + t;
    int v = (idx <= N_NODESC) ? g_deg[idx] : 0;
    ssum[t] = v;
    __syncthreads();
    for (int off = 512; off > 0; off >>= 1) {
        if (t < off) ssum[t] += ssum[t + off];
        __syncthreads();
    }
    if (t == 0) g_bsum[blockIdx.x] = ssum[0];
}
__global__ void scan_blocks() {
    __shared__ int ss[128];
    int t = threadIdx.x;
    g_sum[t] = 0.f;
    g_sq[t] = 0.f;
    g_sum[512 + t] = 0.f;
    g_sq[512 + t] = 0.f;
    ss[t % 128] = 0;
    __syncthreads();
    if (t < 128) ss[t] = (t < 99) ? g_bsum[t] : 0;
    __syncthreads();
    if (t < 128) {
        for (int off = 1; off < 128; off <<= 1) {
            int v = (t >= off) ? ss[t - off] : 0;
            __syncthreads();
            if (t >= off) ss[t] += v;
            __syncthreads();
        }
        g_bsum[t] = (t == 0) ? 0 : ss[t - 1];
    }
}
__global__ void scan_expand() {
    __shared__ int ss[1024];
    int t = threadIdx.x;
    int idx = blockIdx.x * 1024 + t;
    int v = (idx <= N_NODESC) ? g_deg[idx] : 0;
    ss[t] = v;
    __syncthreads();
    for (int off = 1; off < 1024; off <<= 1) {
        int u = (t >= off) ? ss[t - off] : 0;
        __syncthreads();
        if (t >= off) ss[t] += u;
        __syncthreads();
    }
    if (idx <= N_NODESC) {
        int base = g_bsum[blockIdx.x];
        int excl = base + ss[t] - v;
        g_off[idx] = excl;
        if (idx < N_NODESC) g_pos[idx] = excl;
    }
}

// ---------------- fill CSR: byte offsets (+ re-zero deg) ----------------
__global__ void fill_csr(const int* __restrict__ ei, const int* __restrict__ ea) {
    int e = blockIdx.x * blockDim.x + threadIdx.x;
    if (e <= N_NODESC) g_deg[e] = 0;
    if (e >= N_EDGESC) return;
    int src = __ldg(ei + e);
    int dst = __ldg(ei + N_EDGESC + e);
    int key = __ldg(ea + (size_t)e * 3 + 0) * 100
            + __ldg(ea + (size_t)e * 3 + 1) * 10
            + __ldg(ea + (size_t)e * 3 + 2);
    int slot = atomicAdd(&g_pos[dst], 1);
    g_csr[slot] = make_int2(src << 9, key << 9);
}

// ---------------- gather (bf16x2 SIMD, f32x2 accumulate, tf32-rounded z out) ----------------
__global__ __launch_bounds__(256, 6) void gather_mp(const __nv_bfloat16* __restrict__ bond) {
    int n = (int)(((size_t)blockIdx.x * blockDim.x + threadIdx.x) >> 5);
    if (n >= N_NODESC) return;
    int lane = threadIdx.x & 31;
    unsigned fo2 = lane * 16;
    const char* hbase = (const char*)g_hb + fo2;
    const char* bbase = (const char*)bond + fo2;
    uint64_t acc[4];
    {
        uint4 hs = *(const uint4*)(hbase + ((unsigned)n << 9));
        acc[0] = pack_bf16x2_to_f32x2(hs.x);
        acc[1] = pack_bf16x2_to_f32x2(hs.y);
        acc[2] = pack_bf16x2_to_f32x2(hs.z);
        acc[3] = pack_bf16x2_to_f32x2(hs.w);
    }
    int p = g_off[n], pe = g_off[n + 1];
    if (p < pe && (p & 1)) {
        int2 sk = __ldg(&g_csr[p]);
        uint4 h = *(const uint4*)(hbase + (unsigned)sk.x);
        uint4 b = *(const uint4*)(bbase + (unsigned)sk.y);
        acc_edge(acc, h, b);
        p++;
    }
    for (; p + 4 <= pe; p += 4) {
        int4 e01 = *(const int4*)&g_csr[p];
        int4 e23 = *(const int4*)&g_csr[p + 2];
        uint4 h0 = *(const uint4*)(hbase + (unsigned)e01.x);
        uint4 b0 = *(const uint4*)(bbase + (unsigned)e01.y);
        uint4 h1 = *(const uint4*)(hbase + (unsigned)e01.z);
        uint4 b1 = *(const uint4*)(bbase + (unsigned)e01.w);
        uint4 h2 = *(const uint4*)(hbase + (unsigned)e23.x);
        uint4 b2 = *(const uint4*)(bbase + (unsigned)e23.y);
        uint4 h3 = *(const uint4*)(hbase + (unsigned)e23.z);
        uint4 b3 = *(const uint4*)(bbase + (unsigned)e23.w);
        acc_edge(acc, h0, b0);
        acc_edge(acc, h1, b1);
        acc_edge(acc, h2, b2);
        acc_edge(acc, h3, b3);
    }
    for (; p < pe; p++) {
        int2 sk = __ldg(&g_csr[p]);
        uint4 h = *(const uint4*)(hbase + (unsigned)sk.x);
        uint4 b = *(const uint4*)(bbase + (unsigned)sk.y);
        acc_edge(acc, h, b);
    }
    // z is consumed only by GEMM A-loads which round to tf32 anyway -> pre-round (bit-exact)
    float2 r0 = unpack_f32x2_tf32(acc[0]);
    float2 r1 = unpack_f32x2_tf32(acc[1]);
    float2 r2 = unpack_f32x2_tf32(acc[2]);
    float2 r3 = unpack_f32x2_tf32(acc[3]);
    float* zd = g_z + (size_t)n * DIM + lane * 8;
    *(float4*)(zd)     = make_float4(r0.x, r0.y, r1.x, r1.y);
    *(float4*)(zd + 4) = make_float4(r2.x, r2.y, r3.x, r3.y);
}

// ---------------- BN finalize ----------------
__global__ void finstats(const float* __restrict__ gamma, const float* __restrict__ beta,
                         int Dh, int off) {
    int c = blockIdx.x * 256 + threadIdx.x;
    if (c >= Dh) return;
    float inv_n = 1.0f / (float)N_NODESC;
    float mu = g_sum[off + c] * inv_n;
    float var = g_sq[off + c] * inv_n - mu * mu;
    float rs = rsqrtf(var + EPSC);
    float sc = rs * gamma[c];
    g_scale[c] = sc;
    g_shift[c] = beta[c] - mu * sc;
}

// ---------------- tf32 tensor-core GEMM 128x128x16 (padded, conflict-free, 2 CTAs/SM) ----------------
// BIAS=false: bias dropped (legal pre-BN: batch-mean cancels constant column shifts exactly).
template <bool TRANSFORM, bool RELU, int STATS, bool STOREC, bool BF16OUT, bool POOL, bool BIAS>
__global__ __launch_bounds__(256, 2) void gemm_tc(
    const float* __restrict__ A, const float* __restrict__ B,
    const float* __restrict__ bias, float* __restrict__ C,
    const int* __restrict__ batch, float* __restrict__ pool_out,
    int M, int K, int Nc) {
    const int BM = 128, BK = 16;
    const int BKP = BK + 4;
    const int BNP = 128 + 8;
    __shared__ float As[2][BM][BKP];
    __shared__ float Bs[2][BK][BNP];
    __shared__ int sbatch[BM];

    int tid = threadIdx.x;
    int lane = tid & 31;
    int wid = tid >> 5;
    int wm = wid & 1;
    int wn = wid >> 1;
    int bm = blockIdx.y * BM;
    int bn = blockIdx.x * 128;

    if (POOL && tid < BM) sbatch[tid] = (bm + tid < M) ? batch[bm + tid] : -1;

    int idx0 = tid, idx1 = tid + 256;
    int ar0 = idx0 >> 2, ak0 = (idx0 & 3) * 4;
    int ar1 = idx1 >> 2, ak1 = (idx1 & 3) * 4;
    int br0 = idx0 >> 5, bq0 = (idx0 & 31) * 4;
    int br1 = idx1 >> 5, bq1 = (idx1 & 31) * 4;
    bool aok0 = (bm + ar0) < M;
    bool aok1 = (bm + ar1) < M;

    float c[4][4][4];
#pragma unroll
    for (int mt = 0; mt < 4; mt++)
#pragma unroll
        for (int nt = 0; nt < 4; nt++)
#pragma unroll
            for (int r = 0; r < 4; r++) c[mt][nt][r] = 0.f;

    float4 a4s[2];

    auto ldg_a = [&](int k0) {
        a4s[0] = aok0 ? *(const float4*)(A + (size_t)(bm + ar0) * K + k0 + ak0)
                      : make_float4(0.f, 0.f, 0.f, 0.f);
        a4s[1] = aok1 ? *(const float4*)(A + (size_t)(bm + ar1) * K + k0 + ak1)
                      : make_float4(0.f, 0.f, 0.f, 0.f);
        if (TRANSFORM) {
#pragma unroll
            for (int t = 0; t < 2; t++) {
                int kb = k0 + ((t == 0) ? ak0 : ak1);
                float4& v = a4s[t];
                v.x = fmaxf(v.x * g_scale[kb + 0] + g_shift[kb + 0], 0.f);
                v.y = fmaxf(v.y * g_scale[kb + 1] + g_shift[kb + 1], 0.f);
                v.z = fmaxf(v.z * g_scale[kb + 2] + g_shift[kb + 2], 0.f);
                v.w = fmaxf(v.w * g_scale[kb + 3] + g_shift[kb + 3], 0.f);
            }
        }
    };
    auto sts_a = [&](int buf) {
        if (TRANSFORM) {
            *(float4*)&As[buf][ar0][ak0] = make_float4(to_tf32(a4s[0].x), to_tf32(a4s[0].y),
                                                       to_tf32(a4s[0].z), to_tf32(a4s[0].w));
            *(float4*)&As[buf][ar1][ak1] = make_float4(to_tf32(a4s[1].x), to_tf32(a4s[1].y),
                                                       to_tf32(a4s[1].z), to_tf32(a4s[1].w));
        } else {
            // A (g_z) is pre-rounded to tf32 by gather_mp -> raw store
            *(float4*)&As[buf][ar0][ak0] = a4s[0];
            *(float4*)&As[buf][ar1][ak1] = a4s[1];
        }
    };
    auto ldb_async = [&](int buf, int k0) {
        cp_async16(&Bs[buf][br0][bq0], B + (size_t)(k0 + br0) * Nc + bn + bq0);
        cp_async16(&Bs[buf][br1][bq1], B + (size_t)(k0 + br1) * Nc + bn + bq1);
        cp_commit();
    };

    ldb_async(0, 0);
    ldg_a(0);
    sts_a(0);
    cp_wait0();
    __syncthreads();

    int nIter = K / BK;
    int lq = lane >> 2;
    int lr = lane & 3;
    for (int it = 0; it < nIter; it++) {
        int cur = it & 1, nxt = cur ^ 1;
        bool more = (it + 1 < nIter);
        if (more) {
            ldg_a((it + 1) * BK);
            ldb_async(nxt, (it + 1) * BK);
        }
#pragma unroll
        for (int ks = 0; ks < 2; ks++) {
            int k0 = ks * 8;
            uint32_t bf[4][2];
#pragma unroll
            for (int nt = 0; nt < 4; nt++) {
                int ncol = wn * 32 + nt * 8 + lq;
                bf[nt][0] = __float_as_uint(Bs[cur][k0 + lr][ncol]);
                bf[nt][1] = __float_as_uint(Bs[cur][k0 + 4 + lr][ncol]);
            }
#pragma unroll
            for (int mt = 0; mt < 4; mt++) {
                int mrow = wm * 64 + mt * 16 + lq;
                uint32_t af[4];
                af[0] = __float_as_uint(As[cur][mrow][k0 + lr]);
                af[1] = __float_as_uint(As[cur][mrow + 8][k0 + lr]);
                af[2] = __float_as_uint(As[cur][mrow][k0 + 4 + lr]);
                af[3] = __float_as_uint(As[cur][mrow + 8][k0 + 4 + lr]);
#pragma unroll
                for (int nt = 0; nt < 4; nt++) mma_tf32(c[mt][nt], af, bf[nt]);
            }
        }
        if (more) {
            sts_a(nxt);
            cp_wait0();
        }
        __syncthreads();
    }

    // ---------------- epilogue ----------------
    float2 bias2[4];
    int cbase[4];
#pragma unroll
    for (int nt = 0; nt < 4; nt++) {
        cbase[nt] = bn + wn * 32 + nt * 8 + lr * 2;
        if (BIAS) bias2[nt] = *(const float2*)(bias + cbase[nt]);
        else      bias2[nt] = make_float2(0.f, 0.f);
    }

    float sx[4][2], qx[4][2];
    if (STATS >= 0) {
#pragma unroll
        for (int nt = 0; nt < 4; nt++) { sx[nt][0] = sx[nt][1] = 0.f; qx[nt][0] = qx[nt][1] = 0.f; }
    }

    float pl[4][2];
    int curb = -1;
    if (POOL) {
#pragma unroll
        for (int nt = 0; nt < 4; nt++) { pl[nt][0] = 0.f; pl[nt][1] = 0.f; }
    }

#pragma unroll
    for (int mt = 0; mt < 4; mt++) {
#pragma unroll
        for (int half = 0; half < 2; half++) {
            int rloc = wm * 64 + mt * 16 + lq + half * 8;
            int r = bm + rloc;
            if (r >= M) continue;
            float v[4][2];
#pragma unroll
            for (int nt = 0; nt < 4; nt++) {
                v[nt][0] = c[mt][nt][half * 2 + 0];
                v[nt][1] = c[mt][nt][half * 2 + 1];
                if (BIAS) { v[nt][0] += bias2[nt].x; v[nt][1] += bias2[nt].y; }
                if (RELU) {
                    v[nt][0] = fmaxf(v[nt][0], 0.f);
                    v[nt][1] = fmaxf(v[nt][1], 0.f);
                }
                if (STATS >= 0) {
                    sx[nt][0] += v[nt][0]; sx[nt][1] += v[nt][1];
                    qx[nt][0] += v[nt][0] * v[nt][0]; qx[nt][1] += v[nt][1] * v[nt][1];
                }
            }
            if (STOREC) {
#pragma unroll
                for (int nt = 0; nt < 4; nt++)
                    *(float2*)(C + (size_t)r * Nc + cbase[nt]) = make_float2(v[nt][0], v[nt][1]);
            }
            if (BF16OUT) {
#pragma unroll
                for (int nt = 0; nt < 4; nt++)
                    *(__nv_bfloat162*)(g_hb + (size_t)r * DIM + cbase[nt]) =
                        __floats2bfloat162_rn(v[nt][0], v[nt][1]);
            }
            if (POOL) {
                int bg = sbatch[rloc];
                if (bg != curb) {
                    if (curb >= 0) {
#pragma unroll
                        for (int nt = 0; nt < 4; nt++) {
                            red_v2(pool_out + (size_t)curb * DIM + cbase[nt], pl[nt][0], pl[nt][1]);
                            pl[nt][0] = 0.f; pl[nt][1] = 0.f;
                        }
                    }
                    curb = bg;
                }
#pragma unroll
                for (int nt = 0; nt < 4; nt++) { pl[nt][0] += v[nt][0]; pl[nt][1] += v[nt][1]; }
            }
        }
    }
    if (POOL && curb >= 0) {
#pragma unroll
        for (int nt = 0; nt < 4; nt++)
            red_v2(pool_out + (size_t)curb * DIM + cbase[nt], pl[nt][0], pl[nt][1]);
    }

    if (STATS >= 0) {
#pragma unroll
        for (int nt = 0; nt < 4; nt++) {
#pragma unroll
            for (int h = 0; h < 2; h++) {
#pragma unroll
                for (int off = 4; off < 32; off <<= 1) {
                    sx[nt][h] += __shfl_xor_sync(0xffffffffu, sx[nt][h], off);
                    qx[nt][h] += __shfl_xor_sync(0xffffffffu, qx[nt][h], off);
                }
            }
        }
        if (lane < 4) {
#pragma unroll
            for (int nt = 0; nt < 4; nt++) {
                atomicAdd(&g_sum[STATS + cbase[nt] + 0], sx[nt][0]);
                atomicAdd(&g_sum[STATS + cbase[nt] + 1], sx[nt][1]);
                atomicAdd(&g_sq[STATS + cbase[nt] + 0], qx[nt][0]);
                atomicAdd(&g_sq[STATS + cbase[nt] + 1], qx[nt][1]);
            }
        }
    }
}

// ---------------- launch ----------------
extern "C" void kernel_launch(void* const* d_in, const int* in_sizes, int n_in,
                              void* d_out, int out_size) {
    const int* x      = (const int*)d_in[0];
    const int* ei     = (const int*)d_in[1];
    const int* ea     = (const int*)d_in[2];
    const int* batch  = (const int*)d_in[3];
    const float* atom = (const float*)d_in[4];
    const float* be1  = (const float*)d_in[5];
    const float* be2  = (const float*)d_in[6];
    const float* c1_w1 = (const float*)d_in[7];
    const float* c1_b1 = (const float*)d_in[8];
    const float* c1_g  = (const float*)d_in[9];
    const float* c1_be = (const float*)d_in[10];
    const float* c1_w2 = (const float*)d_in[11];
    const float* c1_b2 = (const float*)d_in[12];
    const float* c2_w1 = (const float*)d_in[13];
    const float* c2_b1 = (const float*)d_in[14];
    const float* c2_g  = (const float*)d_in[15];
    const float* c2_be = (const float*)d_in[16];
    const float* c2_w2 = (const float*)d_in[17];
    const float* c2_b2 = (const float*)d_in[18];
    float* out = (float*)d_out;
    (void)c1_b1; (void)c2_b1;  // dropped: BN batch-mean cancels constant column shifts exactly

    float *zz, *yz, *wz;
    __nv_bfloat16 *bbz;
    cudaGetSymbolAddress((void**)&zz, g_z);
    cudaGetSymbolAddress((void**)&yz, g_y);
    cudaGetSymbolAddress((void**)&wz, g_w);
    cudaGetSymbolAddress((void**)&bbz, g_bondb);

    const int M = N_NODESC;
    const int eb = (N_EDGESC + 255) / 256;
    const int gb = (N_NODESC * 32 + 255) / 256;
    const int mtiles = (M + 127) / 128;
    dim3 gA(4, mtiles);   // Nc=512
    dim3 gB(2, mtiles);   // Nc=256
    const int sblocks = (N_NODESC + 1 + 1023) / 1024;

    mega_setup<<<41548, 256>>>(x, atom, be1, be2, c1_w1, c1_w2, c2_w1, c2_w2, ei, out);
    scan_reduce<<<sblocks, 1024>>>();
    scan_blocks<<<1, 512>>>();
    scan_expand<<<sblocks, 1024>>>();
    fill_csr<<<eb, 256>>>(ei, ea);

    // ---- conv1 ----
    gather_mp<<<gb, 256>>>(bbz);
    gemm_tc<false, false, 0, true, false, false, false><<<gA, 256>>>(zz, wz + 0, nullptr, yz, nullptr, nullptr, M, 256, 512);
    finstats<<<2, 256>>>(c1_g, c1_be, 512, 0);
    gemm_tc<true, true, -1, false, true, false, true><<<gB, 256>>>(yz, wz + 131072, c1_b2, nullptr, nullptr, nullptr, M, 512, 256);

    // ---- conv2 ----
    gather_mp<<<gb, 256>>>(bbz + (size_t)1000 * DIM);
    gemm_tc<false, false, 512, true, false, false, false><<<gB, 256>>>(zz, wz + 262144, nullptr, yz, nullptr, nullptr, M, 256, 256);
    finstats<<<1, 256>>>(c2_g, c2_be, 256, 512);
    gemm_tc<true, true, -1, false, false, true, true><<<gB, 256>>>(yz, wz + 327680, c2_b2, nullptr, batch, out, M, 256, 256);
}